// round 10
// baseline (speedup 1.0000x reference)
#include <cuda_runtime.h>
#include <cuda_bf16.h>

// ===========================================================================
// Graph attention layer. R6: edge path on mma.sync bf16 hi/lo (3-term);
// node path keeps R3 f32x2.
//   out = concat(attn_node [N,128], attn_edge [E,128])
// ===========================================================================

#define D        128
#define NMAX     10000

// ---- node path (R3) ----
#define TILE     64
#define XLD      388
#define HLD      132
#define NTHREADS 256
#define WBUF     (64 * D)
#define SMEM_BYTES ((TILE*XLD + TILE*HLD + 2*WBUF) * 4)

__device__ __align__(16) float g_num_src[NMAX * D];
__device__ __align__(16) float g_den_src[NMAX * D];
__device__ __align__(16) float g_num_tgt[NMAX * D];
__device__ __align__(16) float g_den_tgt[NMAX * D];
// fragment-ordered bf16 hi/lo weight images, 10 x [128 n][144 u32]:
// 0-2 e_core_w1 k-chunks, 3-5 e_gate_w1 k-chunks, 6 e_core_w2, 7 e_gate_w2,
// 8 w_src (as B[k][n]=w_src[n][k]), 9 w_tgt
__device__ __align__(16) unsigned g_wimg[10 * 18432];

typedef unsigned long long u64_t;

// ---------- common helpers ----------
__device__ __forceinline__ float siluf(float x)  { return x / (1.f + __expf(-x)); }
__device__ __forceinline__ float sigmf(float x)  { return 1.f / (1.f + __expf(-x)); }
__device__ __forceinline__ void red4(float* a, float x, float y, float z, float w) {
    asm volatile("red.global.add.v4.f32 [%0],{%1,%2,%3,%4};"
                 :: "l"(a), "f"(x), "f"(y), "f"(z), "f"(w) : "memory");
}
__device__ __forceinline__ unsigned smaddr(const void* p) {
    return (unsigned)__cvta_generic_to_shared(p);
}
__device__ __forceinline__ void cpasync16(unsigned dst, const void* src) {
    asm volatile("cp.async.cg.shared.global [%0], [%1], 16;" :: "r"(dst), "l"(src) : "memory");
}
__device__ __forceinline__ void cpcommit() { asm volatile("cp.async.commit_group;" ::: "memory"); }
__device__ __forceinline__ void cpwait0()  { asm volatile("cp.async.wait_group 0;" ::: "memory"); }

// pack (x0,x1) into bf16x2 hi and residual lo
__device__ __forceinline__ void pack_hl(float x0, float x1, unsigned& hi, unsigned& lo) {
    __nv_bfloat16 h0 = __float2bfloat16(x0), h1 = __float2bfloat16(x1);
    __nv_bfloat16 l0 = __float2bfloat16(x0 - __bfloat162float(h0));
    __nv_bfloat16 l1 = __float2bfloat16(x1 - __bfloat162float(h1));
    hi = (unsigned)__bfloat16_as_ushort(h0) | ((unsigned)__bfloat16_as_ushort(h1) << 16);
    lo = (unsigned)__bfloat16_as_ushort(l0) | ((unsigned)__bfloat16_as_ushort(l1) << 16);
}

// mma.sync m16n8k16 bf16: D += A*B
__device__ __forceinline__ void mma_bf16(float d[4], const unsigned a[4],
                                         unsigned b0, unsigned b1) {
    asm volatile("mma.sync.aligned.m16n8k16.row.col.f32.bf16.bf16.f32 "
        "{%0,%1,%2,%3},{%4,%5,%6,%7},{%8,%9},{%0,%1,%2,%3};"
        : "+f"(d[0]), "+f"(d[1]), "+f"(d[2]), "+f"(d[3])
        : "r"(a[0]), "r"(a[1]), "r"(a[2]), "r"(a[3]), "r"(b0), "r"(b1));
}

// ---- edge smem layout (u32 offsets). Row stride = 144 u32.
// Per row, per (ks,t): u32s [hi(kpair t), hi(kpair t+4), lo(t), lo(t+4)]
// at position ks*16 + t*4. kpair j -> ks=j>>3, tt=(j&7)&3, hf=(j&7)>>2:
// hi at ks*16+tt*4+hf, lo at +2.
#define STR   144
#define U_XE  0
#define U_XT  9216
#define U_XS  18432
#define U_H   27648
#define U_B   36864
#define E_UTOT 55296
#define E_DYN  (E_UTOT * 4)

__device__ __forceinline__ void st_pair(unsigned* rowbase, int j, float x0, float x1) {
    int ks = j >> 3, jj = j & 7, tt = jj & 3, hf = jj >> 2;
    unsigned hi, lo;
    pack_hl(x0, x1, hi, lo);
    rowbase[ks*16 + tt*4 + hf]     = hi;
    rowbase[ks*16 + tt*4 + hf + 2] = lo;
}

// stage a 64x128 fp32 block (optionally gathered rows) into frag-ordered smem
__device__ __forceinline__ void stage_X(unsigned* smu, int off, const float* base,
                                        const int* ridx, int e0, int nE, int tid) {
    int r = tid >> 2, part = tid & 3;
    long row = ridx ? (long)ridx[r] : (long)(e0 + r);
    bool ok = ridx ? true : ((e0 + r) < nE);
    const float* p = base + row * D + part * 32;
    unsigned* rb = smu + off + r * STR;
    #pragma unroll
    for (int q = 0; q < 8; ++q) {
        float4 v = ok ? __ldg((const float4*)(p + q * 4)) : make_float4(0.f,0.f,0.f,0.f);
        int j0 = part * 16 + q * 2;
        st_pair(rb, j0,     v.x, v.y);
        st_pair(rb, j0 + 1, v.z, v.w);
    }
}

// copy one weight image (73728 B) into B smem
__device__ __forceinline__ void stage_Bimg(unsigned* smu, int img, int tid) {
    unsigned dst = smaddr(smu + U_B);
    const char* src = (const char*)(g_wimg + (size_t)img * 18432);
    #pragma unroll
    for (int t = 0; t < 18; ++t) {
        int o = (tid + t * 256) * 16;
        cpasync16(dst + o, src + o);
    }
    cpcommit();
    cpwait0();
}

// acc[nt][0..3]: rows rw*16+g, rw*16+g+8 x cols cw*64+nt*8+2t, 2t+1
__device__ __forceinline__ void gemm_chunk(const unsigned* __restrict__ smu, int aoff,
                                           float acc[8][4], int rw, int cw, int lane) {
    int g = lane >> 2, t = lane & 3;
    const uint4* A0 = (const uint4*)(smu + aoff + (rw*16 + g) * STR);
    const uint4* A1 = (const uint4*)(smu + aoff + (rw*16 + g + 8) * STR);
    const uint4* B0 = (const uint4*)(smu + U_B + (cw*64 + g) * STR);
    #pragma unroll
    for (int ks = 0; ks < 8; ++ks) {
        uint4 ra0 = A0[ks*4 + t];
        uint4 ra1 = A1[ks*4 + t];
        unsigned Ah[4] = {ra0.x, ra1.x, ra0.y, ra1.y};
        unsigned Al[4] = {ra0.z, ra1.z, ra0.w, ra1.w};
        #pragma unroll
        for (int nt = 0; nt < 8; ++nt) {
            uint4 rb = B0[nt*8*(STR/4) + ks*4 + t];
            mma_bf16(acc[nt], Ah, rb.x, rb.y);
            mma_bf16(acc[nt], Ah, rb.z, rb.w);
            mma_bf16(acc[nt], Al, rb.x, rb.y);
        }
    }
}

__device__ __forceinline__ void zero8(float acc[8][4]) {
    #pragma unroll
    for (int i = 0; i < 8; ++i)
        #pragma unroll
        for (int p = 0; p < 4; ++p) acc[i][p] = 0.f;
}

// silu(acc) -> H smem (frag-ordered)
__device__ __forceinline__ void store_H(unsigned* smu, float acc[8][4],
                                        int rw, int cw, int lane) {
    int g = lane >> 2, t = lane & 3;
    unsigned* h0 = smu + U_H + (rw*16 + g) * STR;
    unsigned* h1 = h0 + 8 * STR;
    #pragma unroll
    for (int nt = 0; nt < 8; ++nt) {
        int j = cw*32 + nt*4 + t;
        st_pair(h0, j, siluf(acc[nt][0]), siluf(acc[nt][1]));
        st_pair(h1, j, siluf(acc[nt][2]), siluf(acc[nt][3]));
    }
}

// LayerNorm across 128 cols (2 col-warps combine via smLN); normalizes acc
__device__ __forceinline__ void ln_frags(float acc[8][4], int rw, int cw, int lane,
                                         const float* __restrict__ gma,
                                         const float* __restrict__ bta,
                                         float2 (*smLN)[2]) {
    int g = lane >> 2, t = lane & 3;
    float s0=0.f, q0=0.f, s1=0.f, q1=0.f;
    #pragma unroll
    for (int nt = 0; nt < 8; ++nt) {
        s0 += acc[nt][0] + acc[nt][1];
        q0 += acc[nt][0]*acc[nt][0] + acc[nt][1]*acc[nt][1];
        s1 += acc[nt][2] + acc[nt][3];
        q1 += acc[nt][2]*acc[nt][2] + acc[nt][3]*acc[nt][3];
    }
    #pragma unroll
    for (int m = 1; m <= 2; m <<= 1) {
        s0 += __shfl_xor_sync(0xffffffffu, s0, m);
        q0 += __shfl_xor_sync(0xffffffffu, q0, m);
        s1 += __shfl_xor_sync(0xffffffffu, s1, m);
        q1 += __shfl_xor_sync(0xffffffffu, q1, m);
    }
    int r0 = rw*16 + g;
    if (t == 0) {
        smLN[r0][cw]     = make_float2(s0, q0);
        smLN[r0 + 8][cw] = make_float2(s1, q1);
    }
    __syncthreads();
    float2 xa = smLN[r0][0], xb = smLN[r0][1];
    float mean0 = (xa.x + xb.x) * 0.0078125f;
    float inv0  = rsqrtf((xa.y + xb.y) * 0.0078125f - mean0*mean0 + 1e-5f);
    xa = smLN[r0 + 8][0]; xb = smLN[r0 + 8][1];
    float mean1 = (xa.x + xb.x) * 0.0078125f;
    float inv1  = rsqrtf((xa.y + xb.y) * 0.0078125f - mean1*mean1 + 1e-5f);
    #pragma unroll
    for (int nt = 0; nt < 8; ++nt) {
        int c = cw*64 + nt*8 + 2*t;
        float ga = __ldg(gma + c), gb = __ldg(gma + c + 1);
        float ba = __ldg(bta + c), bb = __ldg(bta + c + 1);
        acc[nt][0] = (acc[nt][0] - mean0) * inv0 * ga + ba;
        acc[nt][1] = (acc[nt][1] - mean0) * inv0 * gb + bb;
        acc[nt][2] = (acc[nt][2] - mean1) * inv1 * ga + ba;
        acc[nt][3] = (acc[nt][3] - mean1) * inv1 * gb + bb;
    }
}

// ===========================================================================
// prep: zero accumulators + build frag-ordered weight images
// ===========================================================================
__global__ void prep_kernel(const float* __restrict__ w_src,
                            const float* __restrict__ w_tgt,
                            const float* __restrict__ e1c,
                            const float* __restrict__ e2c,
                            const float* __restrict__ e1g,
                            const float* __restrict__ e2g, int nN)
{
    int i = blockIdx.x * blockDim.x + threadIdx.x;
    if (i < 10 * 8192) {
        int img = i >> 13;
        int rem = i & 8191;
        int n = rem >> 6, j = rem & 63;
        int k = 2 * j;
        float v0, v1;
        if (img < 3)       { v0 = e1c[(img*128 + k)*128 + n]; v1 = e1c[(img*128 + k + 1)*128 + n]; }
        else if (img < 6)  { int c = img - 3;
                             v0 = e1g[(c*128 + k)*128 + n];  v1 = e1g[(c*128 + k + 1)*128 + n]; }
        else if (img == 6) { v0 = e2c[k*128 + n];            v1 = e2c[(k + 1)*128 + n]; }
        else if (img == 7) { v0 = e2g[k*128 + n];            v1 = e2g[(k + 1)*128 + n]; }
        else if (img == 8) { v0 = w_src[n*128 + k];          v1 = w_src[n*128 + k + 1]; }
        else               { v0 = w_tgt[n*128 + k];          v1 = w_tgt[n*128 + k + 1]; }
        unsigned hi, lo;
        pack_hl(v0, v1, hi, lo);
        int ks = j >> 3, jj = j & 7, tt = jj & 3, hf = jj >> 2;
        int pos = img * 18432 + n * STR + ks*16 + tt*4 + hf;
        g_wimg[pos]     = hi;
        g_wimg[pos + 2] = lo;
    }
    if (i < nN * D) {
        g_num_src[i] = 0.f; g_den_src[i] = 0.f;
        g_num_tgt[i] = 0.f; g_den_tgt[i] = 0.f;
    }
}

// ===========================================================================
// edge kernel: 64 edges/CTA, 256 threads, mma.sync bf16 hi/lo
// ===========================================================================
__global__ void __launch_bounds__(256) edge_mma_kernel(
    const float* __restrict__ node_feat, const float* __restrict__ edge_feat,
    const float* __restrict__ lgc, const float* __restrict__ lbc,
    const float* __restrict__ lgg, const float* __restrict__ lbg,
    const float* __restrict__ edge_res_w,
    const int* __restrict__ src_idx, const int* __restrict__ tgt_idx,
    float* __restrict__ out_edge, int nE)
{
    extern __shared__ unsigned smu[];
    __shared__ int sidx[64], tidx[64];
    __shared__ float2 smLN[64][2];

    int tid = threadIdx.x;
    int wid = tid >> 5, lane = tid & 31;
    int rw = wid & 3, cw = wid >> 2;
    int e0 = blockIdx.x * 64;

    if (tid < 64) {
        int e = e0 + tid;
        sidx[tid] = (e < nE) ? src_idx[e] : 0;
        tidx[tid] = (e < nE) ? tgt_idx[e] : 0;
    }
    __syncthreads();

    stage_X(smu, U_XE, edge_feat, nullptr, e0, nE, tid);
    stage_X(smu, U_XT, node_feat, tidx, 0, 0, tid);
    stage_X(smu, U_XS, node_feat, sidx, 0, 0, tid);

    #define STAGEB(i) do { __syncthreads(); stage_Bimg(smu, i, tid); __syncthreads(); } while(0)

    float acc[8][4], cn[8][4];

    // ---- core branch ----
    zero8(acc);
    STAGEB(0); gemm_chunk(smu, U_XE, acc, rw, cw, lane);
    STAGEB(1); gemm_chunk(smu, U_XT, acc, rw, cw, lane);
    STAGEB(2); gemm_chunk(smu, U_XS, acc, rw, cw, lane);
    store_H(smu, acc, rw, cw, lane);
    zero8(acc);
    STAGEB(6); gemm_chunk(smu, U_H, acc, rw, cw, lane);
    ln_frags(acc, rw, cw, lane, lgc, lbc, smLN);
    #pragma unroll
    for (int nt = 0; nt < 8; ++nt)
        #pragma unroll
        for (int p = 0; p < 4; ++p) cn[nt][p] = acc[nt][p];

    // ---- gate branch ----
    zero8(acc);
    STAGEB(3); gemm_chunk(smu, U_XE, acc, rw, cw, lane);
    STAGEB(4); gemm_chunk(smu, U_XT, acc, rw, cw, lane);
    STAGEB(5); gemm_chunk(smu, U_XS, acc, rw, cw, lane);
    store_H(smu, acc, rw, cw, lane);
    zero8(acc);
    STAGEB(7); gemm_chunk(smu, U_H, acc, rw, cw, lane);
    ln_frags(acc, rw, cw, lane, lgg, lbg, smLN);
    #pragma unroll
    for (int nt = 0; nt < 8; ++nt)
        #pragma unroll
        for (int p = 0; p < 4; ++p) cn[nt][p] = siluf(cn[nt][p]) * sigmf(acc[nt][p]);

    // attn -> smem [64][stride 129] (reuse XT region)
    {
        float* at = (float*)(smu + U_XT);
        int g = lane >> 2, t = lane & 3;
        int r0 = rw*16 + g;
        #pragma unroll
        for (int nt = 0; nt < 8; ++nt) {
            int c = cw*64 + nt*8 + 2*t;
            at[r0*129 + c]       = cn[nt][0];
            at[r0*129 + c + 1]   = cn[nt][1];
            at[(r0+8)*129 + c]   = cn[nt][2];
            at[(r0+8)*129 + c+1] = cn[nt][3];
        }
    }

    // ---- z GEMMs ----
    zero8(acc);
    STAGEB(8); gemm_chunk(smu, U_XE, acc, rw, cw, lane);
    {
        float* z1 = (float*)(smu + U_XS);
        int g = lane >> 2, t = lane & 3;
        int r0 = rw*16 + g;
        #pragma unroll
        for (int nt = 0; nt < 8; ++nt) {
            int c = cw*64 + nt*8 + 2*t;
            z1[r0*129 + c]       = __expf(acc[nt][0]);
            z1[r0*129 + c + 1]   = __expf(acc[nt][1]);
            z1[(r0+8)*129 + c]   = __expf(acc[nt][2]);
            z1[(r0+8)*129 + c+1] = __expf(acc[nt][3]);
        }
    }
    zero8(acc);
    STAGEB(9); gemm_chunk(smu, U_XE, acc, rw, cw, lane);
    {
        float* z2 = (float*)(smu + U_H);
        int g = lane >> 2, t = lane & 3;
        int r0 = rw*16 + g;
        #pragma unroll
        for (int nt = 0; nt < 8; ++nt) {
            int c = cw*64 + nt*8 + 2*t;
            z2[r0*129 + c]       = __expf(acc[nt][0]);
            z2[r0*129 + c + 1]   = __expf(acc[nt][1]);
            z2[(r0+8)*129 + c]   = __expf(acc[nt][2]);
            z2[(r0+8)*129 + c+1] = __expf(acc[nt][3]);
        }
    }
    __syncthreads();

    // ---- pass C: out_edge = attn + edge_res_w * edge_feat (coalesced) ----
    const float* at = (const float*)(smu + U_XT);
    const float* z1 = (const float*)(smu + U_XS);
    const float* z2 = (const float*)(smu + U_H);
    for (int idx = tid; idx < 64 * 32; idx += 256) {
        int r2 = idx >> 5, q = (idx & 31) << 2;
        int e2 = e0 + r2;
        if (e2 < nE) {
            float4 ef = __ldg((const float4*)(edge_feat + (size_t)e2 * D + q));
            float4 rwv = __ldg((const float4*)(edge_res_w + q));
            const float* ap = at + r2*129 + q;
            float4 o = {ap[0] + rwv.x*ef.x, ap[1] + rwv.y*ef.y,
                        ap[2] + rwv.z*ef.z, ap[3] + rwv.w*ef.w};
            *(float4*)(out_edge + (size_t)e2 * D + q) = o;
        }
    }

    // ---- pass D: softmax num/den atomics ----
    for (int idx = tid; idx < 64 * 32; idx += 256) {
        int r2 = idx >> 5, q = (idx & 31) << 2;
        int e2 = e0 + r2;
        if (e2 < nE) {
            int ns = sidx[r2], ntg = tidx[r2];
            const float* ap = at + r2*129 + q;
            const float* p1 = z1 + r2*129 + q;
            const float* p2 = z2 + r2*129 + q;
            red4(g_den_src + (size_t)ns * D + q, p1[0], p1[1], p1[2], p1[3]);
            red4(g_num_src + (size_t)ns * D + q,
                 p1[0]*ap[0], p1[1]*ap[1], p1[2]*ap[2], p1[3]*ap[3]);
            red4(g_den_tgt + (size_t)ntg * D + q, p2[0], p2[1], p2[2], p2[3]);
            red4(g_num_tgt + (size_t)ntg * D + q,
                 p2[0]*ap[0], p2[1]*ap[1], p2[2]*ap[2], p2[3]*ap[3]);
        }
    }
    #undef STAGEB
}

// ===========================================================================
// node path (R3 f32x2) — unchanged
// ===========================================================================
__device__ __forceinline__ u64_t pack2(float x) {
    u64_t r; asm("mov.b64 %0,{%1,%1};" : "=l"(r) : "f"(x)); return r;
}
__device__ __forceinline__ void unpack2(u64_t v, float& lo, float& hi) {
    asm("mov.b64 {%0,%1},%2;" : "=f"(lo), "=f"(hi) : "l"(v));
}
__device__ __forceinline__ void fma2(u64_t& d, u64_t a, u64_t b) {
    asm("fma.rn.f32x2 %0,%1,%2,%0;" : "+l"(d) : "l"(a), "l"(b));
}
__device__ __forceinline__ float f4get(const float4& v, int i) {
    switch (i) { case 0: return v.x; case 1: return v.y; case 2: return v.z; default: return v.w; }
}

__device__ __forceinline__ void gemm_tile(
    const float* __restrict__ Xsm, int xld, const float* __restrict__ gW,
    float* __restrict__ Wsm, int Ktot, u64_t acc[4][4], int r0, int cb, int tid)
{
    const int nb = Ktot >> 6;
    const int srow = tid >> 5, scol = (tid & 31) << 2;
    #pragma unroll
    for (int t = 0; t < 8; ++t)
        cpasync16(smaddr(Wsm + (srow + t * 8) * D + scol),
                  gW + (size_t)(srow + t * 8) * D + scol);
    cpcommit(); cpwait0(); __syncthreads();

    for (int b = 0; b < nb; ++b) {
        const float* cur = Wsm + (b & 1) * WBUF;
        if (b + 1 < nb) {
            const float* src = gW + (size_t)(b + 1) * 64 * D;
            float* dst = Wsm + ((b + 1) & 1) * WBUF;
            #pragma unroll
            for (int t = 0; t < 8; ++t)
                cpasync16(smaddr(dst + (srow + t * 8) * D + scol),
                          src + (size_t)(srow + t * 8) * D + scol);
            cpcommit();
        }
        const float* x0 = Xsm + (r0 + 0) * xld + (b << 6);
        const float* x1 = Xsm + (r0 + 1) * xld + (b << 6);
        const float* x2 = Xsm + (r0 + 2) * xld + (b << 6);
        const float* x3 = Xsm + (r0 + 3) * xld + (b << 6);
        #pragma unroll 2
        for (int k = 0; k < 64; k += 4) {
            float4 xr0 = *(const float4*)(x0 + k);
            float4 xr1 = *(const float4*)(x1 + k);
            float4 xr2 = *(const float4*)(x2 + k);
            float4 xr3 = *(const float4*)(x3 + k);
            #pragma unroll
            for (int kk = 0; kk < 4; ++kk) {
                ulonglong2 wA = *(const ulonglong2*)(cur + (k + kk) * D + cb);
                ulonglong2 wB = *(const ulonglong2*)(cur + (k + kk) * D + cb + 32);
                u64_t xa = pack2(f4get(xr0, kk)), xb = pack2(f4get(xr1, kk));
                u64_t xc = pack2(f4get(xr2, kk)), xd = pack2(f4get(xr3, kk));
                fma2(acc[0][0], xa, wA.x); fma2(acc[0][1], xa, wA.y);
                fma2(acc[0][2], xa, wB.x); fma2(acc[0][3], xa, wB.y);
                fma2(acc[1][0], xb, wA.x); fma2(acc[1][1], xb, wA.y);
                fma2(acc[1][2], xb, wB.x); fma2(acc[1][3], xb, wB.y);
                fma2(acc[2][0], xc, wA.x); fma2(acc[2][1], xc, wA.y);
                fma2(acc[2][2], xc, wB.x); fma2(acc[2][3], xc, wB.y);
                fma2(acc[3][0], xd, wA.x); fma2(acc[3][1], xd, wA.y);
                fma2(acc[3][2], xd, wB.x); fma2(acc[3][3], xd, wB.y);
            }
        }
        cpwait0(); __syncthreads();
    }
}

__device__ __forceinline__ void zero_acc(u64_t acc[4][4]) {
    #pragma unroll
    for (int i = 0; i < 4; ++i)
        #pragma unroll
        for (int p = 0; p < 4; ++p) acc[i][p] = 0ULL;
}
__device__ __forceinline__ void acc_to_f(u64_t acc[4][4], float a[4][8]) {
    #pragma unroll
    for (int i = 0; i < 4; ++i)
        #pragma unroll
        for (int p = 0; p < 4; ++p) unpack2(acc[i][p], a[i][2*p], a[i][2*p+1]);
}

__device__ __forceinline__ void layernorm_rows(float a[4][8],
    const float* __restrict__ g, const float* __restrict__ b,
    int cb, int col_warp, int r0, int lane, float2 (*smLN)[2])
{
    float4 g0 = *(const float4*)(g + cb), g1 = *(const float4*)(g + cb + 32);
    float4 b0 = *(const float4*)(b + cb), b1 = *(const float4*)(b + cb + 32);
    float gv[8] = {g0.x, g0.y, g0.z, g0.w, g1.x, g1.y, g1.z, g1.w};
    float bv[8] = {b0.x, b0.y, b0.z, b0.w, b1.x, b1.y, b1.z, b1.w};
    float s1[4], s2[4];
    #pragma unroll
    for (int i = 0; i < 4; ++i) {
        float s = 0.f, q = 0.f;
        #pragma unroll
        for (int j = 0; j < 8; ++j) { s += a[i][j]; q += a[i][j] * a[i][j]; }
        #pragma unroll
        for (int m = 1; m <= 4; m <<= 1) {
            s += __shfl_xor_sync(0xffffffffu, s, m);
            q += __shfl_xor_sync(0xffffffffu, q, m);
        }
        s1[i] = s; s2[i] = q;
    }
    if ((lane & 7) == 0) {
        #pragma unroll
        for (int i = 0; i < 4; ++i) smLN[r0 + i][col_warp] = make_float2(s1[i], s2[i]);
    }
    __syncthreads();
    #pragma unroll
    for (int i = 0; i < 4; ++i) {
        float2 pa = smLN[r0 + i][0], pb = smLN[r0 + i][1];
        float mean = (pa.x + pb.x) * 0.0078125f;
        float inv = rsqrtf((pa.y + pb.y) * 0.0078125f - mean * mean + 1e-5f);
        #pragma unroll
        for (int j = 0; j < 8; ++j) a[i][j] = (a[i][j] - mean) * inv * gv[j] + bv[j];
    }
}

__global__ void __launch_bounds__(NTHREADS) node_kernel(
    const float* __restrict__ node_feat,
    const float* __restrict__ w1c, const float* __restrict__ w2c,
    const float* __restrict__ w1g, const float* __restrict__ w2g,
    const float* __restrict__ lgc, const float* __restrict__ lbc,
    const float* __restrict__ lgg, const float* __restrict__ lbg,
    const float* __restrict__ node_res_w,
    float* __restrict__ out_node, int nN)
{
    extern __shared__ float sm[];
    float* Xsm = sm;
    float* Hsm = sm + TILE * XLD;
    float* Wsm = Hsm + TILE * HLD;
    __shared__ float2 smLN[TILE][2];

    int tid = threadIdx.x;
    int n0 = blockIdx.x * TILE;

    for (int idx = tid; idx < TILE * 96; idx += NTHREADS) {
        int r = idx / 96, p = idx % 96;
        int n = n0 + r;
        float4 v = {0.f, 0.f, 0.f, 0.f};
        if (n < nN) {
            if (p < 32) {
                v = *(const float4*)(node_feat + (size_t)n * D + p * 4);
            } else if (p < 64) {
                int o = (p - 32) * 4;
                float4 nu = *(const float4*)(g_num_tgt + (size_t)n * D + o);
                float4 de = *(const float4*)(g_den_tgt + (size_t)n * D + o);
                v.x = nu.x / (de.x + 1e-16f); v.y = nu.y / (de.y + 1e-16f);
                v.z = nu.z / (de.z + 1e-16f); v.w = nu.w / (de.w + 1e-16f);
            } else {
                int o = (p - 64) * 4;
                float4 nu = *(const float4*)(g_num_src + (size_t)n * D + o);
                float4 de = *(const float4*)(g_den_src + (size_t)n * D + o);
                v.x = nu.x / (de.x + 1e-16f); v.y = nu.y / (de.y + 1e-16f);
                v.z = nu.z / (de.z + 1e-16f); v.w = nu.w / (de.w + 1e-16f);
            }
        }
        *(float4*)(Xsm + r * XLD + p * 4) = v;
    }

    int wid = tid >> 5, lane = tid & 31;
    int row_warp = wid >> 1, col_warp = wid & 1;
    int ty = lane >> 3, tx = lane & 7;
    int r0 = row_warp * 16 + ty * 4;
    int cb = col_warp * 64 + tx * 4;

    u64_t acc[4][4];
    float a[4][8], attn[4][8];

    zero_acc(acc);
    gemm_tile(Xsm, XLD, w1c, Wsm, 384, acc, r0, cb, tid);
    acc_to_f(acc, a);
    #pragma unroll
    for (int i = 0; i < 4; ++i) {
        float4 h0 = {siluf(a[i][0]), siluf(a[i][1]), siluf(a[i][2]), siluf(a[i][3])};
        float4 h1 = {siluf(a[i][4]), siluf(a[i][5]), siluf(a[i][6]), siluf(a[i][7])};
        *(float4*)(Hsm + (r0 + i) * HLD + cb)      = h0;
        *(float4*)(Hsm + (r0 + i) * HLD + cb + 32) = h1;
    }
    zero_acc(acc);
    gemm_tile(Hsm, HLD, w2c, Wsm, 128, acc, r0, cb, tid);
    acc_to_f(acc, a);
    layernorm_rows(a, lgc, lbc, cb, col_warp, r0, lane, smLN);
    #pragma unroll
    for (int i = 0; i < 4; ++i)
        #pragma unroll
        for (int j = 0; j < 8; ++j) attn[i][j] = a[i][j];

    zero_acc(acc);
    gemm_tile(Xsm, XLD, w1g, Wsm, 384, acc, r0, cb, tid);
    acc_to_f(acc, a);
    #pragma unroll
    for (int i = 0; i < 4; ++i) {
        float4 h0 = {siluf(a[i][0]), siluf(a[i][1]), siluf(a[i][2]), siluf(a[i][3])};
        float4 h1 = {siluf(a[i][4]), siluf(a[i][5]), siluf(a[i][6]), siluf(a[i][7])};
        *(float4*)(Hsm + (r0 + i) * HLD + cb)      = h0;
        *(float4*)(Hsm + (r0 + i) * HLD + cb + 32) = h1;
    }
    zero_acc(acc);
    gemm_tile(Hsm, HLD, w2g, Wsm, 128, acc, r0, cb, tid);
    acc_to_f(acc, a);
    layernorm_rows(a, lgg, lbg, cb, col_warp, r0, lane, smLN);
    #pragma unroll
    for (int i = 0; i < 4; ++i)
        #pragma unroll
        for (int j = 0; j < 8; ++j)
            attn[i][j] = siluf(attn[i][j]) * sigmf(a[i][j]);

    float4 rw0 = *(const float4*)(node_res_w + cb);
    float4 rw1 = *(const float4*)(node_res_w + cb + 32);
    float rwv[8] = {rw0.x, rw0.y, rw0.z, rw0.w, rw1.x, rw1.y, rw1.z, rw1.w};
    #pragma unroll
    for (int i = 0; i < 4; ++i) {
        int n = n0 + r0 + i;
        if (n < nN) {
            const float* nfA = Xsm + (r0 + i) * XLD + cb;
            const float* nfB = nfA + 32;
            float4 o0 = {attn[i][0] + rwv[0]*nfA[0], attn[i][1] + rwv[1]*nfA[1],
                         attn[i][2] + rwv[2]*nfA[2], attn[i][3] + rwv[3]*nfA[3]};
            float4 o1 = {attn[i][4] + rwv[4]*nfB[0], attn[i][5] + rwv[5]*nfB[1],
                         attn[i][6] + rwv[6]*nfB[2], attn[i][7] + rwv[7]*nfB[3]};
            *(float4*)(out_node + (size_t)n * D + cb)      = o0;
            *(float4*)(out_node + (size_t)n * D + cb + 32) = o1;
        }
    }
}

// ---------------------------------------------------------------------------
extern "C" void kernel_launch(void* const* d_in, const int* in_sizes, int n_in,
                              void* d_out, int out_size)
{
    const float* node_feat = (const float*)d_in[0];
    const float* edge_feat = (const float*)d_in[1];
    const float* w_src     = (const float*)d_in[2];
    const float* w_tgt     = (const float*)d_in[3];
    const float* e_core_w1 = (const float*)d_in[4];
    const float* e_core_w2 = (const float*)d_in[5];
    const float* e_gate_w1 = (const float*)d_in[6];
    const float* e_gate_w2 = (const float*)d_in[7];
    const float* e_ln_cg   = (const float*)d_in[8];
    const float* e_ln_cb   = (const float*)d_in[9];
    const float* e_ln_gg   = (const float*)d_in[10];
    const float* e_ln_gb   = (const float*)d_in[11];
    const float* n_core_w1 = (const float*)d_in[12];
    const float* n_core_w2 = (const float*)d_in[13];
    const float* n_gate_w1 = (const float*)d_in[14];
    const float* n_gate_w2 = (const float*)d_in[15];
    const float* n_ln_cg   = (const float*)d_in[16];
    const float* n_ln_cb   = (const float*)d_in[17];
    const float* n_ln_gg   = (const float*)d_in[18];
    const float* n_ln_gb   = (const float*)d_in[19];
    const float* node_res_w= (const float*)d_in[20];
    const float* edge_res_w= (const float*)d_in[21];
    const int*   src_idx   = (const int*)d_in[22];
    const int*   tgt_idx   = (const int*)d_in[23];

    int nN = in_sizes[0] / D;
    int nE = in_sizes[1] / D;

    float* out_node = (float*)d_out;
    float* out_edge = out_node + (size_t)nN * D;

    cudaFuncSetAttribute(edge_mma_kernel, cudaFuncAttributeMaxDynamicSharedMemorySize, E_DYN);
    cudaFuncSetAttribute(node_kernel, cudaFuncAttributeMaxDynamicSharedMemorySize, SMEM_BYTES);

    prep_kernel<<<(nN * D + 255) / 256, 256>>>(w_src, w_tgt,
        e_core_w1, e_core_w2, e_gate_w1, e_gate_w2, nN);

    edge_mma_kernel<<<(nE + 63) / 64, 256, E_DYN>>>(
        node_feat, edge_feat,
        e_ln_cg, e_ln_cb, e_ln_gg, e_ln_gb,
        edge_res_w, src_idx, tgt_idx, out_edge, nE);

    node_kernel<<<(nN + TILE - 1) / TILE, NTHREADS, SMEM_BYTES>>>(
        node_feat,
        n_core_w1, n_core_w2, n_gate_w1, n_gate_w2,
        n_ln_cg, n_ln_cb, n_ln_gg, n_ln_gb,
        node_res_w, out_node, nN);
}

// round 11
// speedup vs baseline: 1.4648x; 1.4648x over previous
#include <cuda_runtime.h>
#include <cuda_bf16.h>

// ===========================================================================
// Graph attention layer. R6: edge path on mma.sync bf16 hi/lo (3-term);
// node path keeps R3 f32x2.
//   out = concat(attn_node [N,128], attn_edge [E,128])
// ===========================================================================

#define D        128
#define NMAX     10000

// ---- node path (R3) ----
#define TILE     64
#define XLD      388
#define HLD      132
#define NTHREADS 256
#define WBUF     (64 * D)
#define SMEM_BYTES ((TILE*XLD + TILE*HLD + 2*WBUF) * 4)

__device__ __align__(16) float g_num_src[NMAX * D];
__device__ __align__(16) float g_den_src[NMAX * D];
__device__ __align__(16) float g_num_tgt[NMAX * D];
__device__ __align__(16) float g_den_tgt[NMAX * D];
// fragment-ordered bf16 hi/lo weight images, 10 x [128 n][144 u32]:
// 0-2 e_core_w1 k-chunks, 3-5 e_gate_w1 k-chunks, 6 e_core_w2, 7 e_gate_w2,
// 8 w_src (as B[k][n]=w_src[n][k]), 9 w_tgt
__device__ __align__(16) unsigned g_wimg[10 * 18432];

typedef unsigned long long u64_t;

// ---------- common helpers ----------
__device__ __forceinline__ float siluf(float x)  { return x / (1.f + __expf(-x)); }
__device__ __forceinline__ float sigmf(float x)  { return 1.f / (1.f + __expf(-x)); }
__device__ __forceinline__ void red4(float* a, float x, float y, float z, float w) {
    asm volatile("red.global.add.v4.f32 [%0],{%1,%2,%3,%4};"
                 :: "l"(a), "f"(x), "f"(y), "f"(z), "f"(w) : "memory");
}
__device__ __forceinline__ unsigned smaddr(const void* p) {
    return (unsigned)__cvta_generic_to_shared(p);
}
__device__ __forceinline__ void cpasync16(unsigned dst, const void* src) {
    asm volatile("cp.async.cg.shared.global [%0], [%1], 16;" :: "r"(dst), "l"(src) : "memory");
}
__device__ __forceinline__ void cpcommit() { asm volatile("cp.async.commit_group;" ::: "memory"); }
__device__ __forceinline__ void cpwait0()  { asm volatile("cp.async.wait_group 0;" ::: "memory"); }

// pack (x0,x1) into bf16x2 hi and residual lo
__device__ __forceinline__ void pack_hl(float x0, float x1, unsigned& hi, unsigned& lo) {
    __nv_bfloat16 h0 = __float2bfloat16(x0), h1 = __float2bfloat16(x1);
    __nv_bfloat16 l0 = __float2bfloat16(x0 - __bfloat162float(h0));
    __nv_bfloat16 l1 = __float2bfloat16(x1 - __bfloat162float(h1));
    hi = (unsigned)__bfloat16_as_ushort(h0) | ((unsigned)__bfloat16_as_ushort(h1) << 16);
    lo = (unsigned)__bfloat16_as_ushort(l0) | ((unsigned)__bfloat16_as_ushort(l1) << 16);
}

// mma.sync m16n8k16 bf16: D += A*B
__device__ __forceinline__ void mma_bf16(float d[4], const unsigned a[4],
                                         unsigned b0, unsigned b1) {
    asm volatile("mma.sync.aligned.m16n8k16.row.col.f32.bf16.bf16.f32 "
        "{%0,%1,%2,%3},{%4,%5,%6,%7},{%8,%9},{%0,%1,%2,%3};"
        : "+f"(d[0]), "+f"(d[1]), "+f"(d[2]), "+f"(d[3])
        : "r"(a[0]), "r"(a[1]), "r"(a[2]), "r"(a[3]), "r"(b0), "r"(b1));
}

// ---- edge smem layout (u32 offsets). Row stride = 144 u32.
// Per row, per (ks,t): u32s [hi(kpair t), hi(kpair t+4), lo(t), lo(t+4)]
// at position ks*16 + t*4. kpair j -> ks=j>>3, tt=(j&7)&3, hf=(j&7)>>2:
// hi at ks*16+tt*4+hf, lo at +2.
#define STR   144
#define U_XE  0
#define U_XT  9216
#define U_XS  18432
#define U_H   27648
#define U_B   36864
#define E_UTOT 55296
#define E_DYN  (E_UTOT * 4)

__device__ __forceinline__ void st_pair(unsigned* rowbase, int j, float x0, float x1) {
    int ks = j >> 3, jj = j & 7, tt = jj & 3, hf = jj >> 2;
    unsigned hi, lo;
    pack_hl(x0, x1, hi, lo);
    rowbase[ks*16 + tt*4 + hf]     = hi;
    rowbase[ks*16 + tt*4 + hf + 2] = lo;
}

// stage a 64x128 fp32 block (optionally gathered rows) into frag-ordered smem
__device__ __forceinline__ void stage_X(unsigned* smu, int off, const float* base,
                                        const int* ridx, int e0, int nE, int tid) {
    int r = tid >> 2, part = tid & 3;
    long row = ridx ? (long)ridx[r] : (long)(e0 + r);
    bool ok = ridx ? true : ((e0 + r) < nE);
    const float* p = base + row * D + part * 32;
    unsigned* rb = smu + off + r * STR;
    #pragma unroll
    for (int q = 0; q < 8; ++q) {
        float4 v = ok ? __ldg((const float4*)(p + q * 4)) : make_float4(0.f,0.f,0.f,0.f);
        int j0 = part * 16 + q * 2;
        st_pair(rb, j0,     v.x, v.y);
        st_pair(rb, j0 + 1, v.z, v.w);
    }
}

// copy one weight image (73728 B) into B smem
__device__ __forceinline__ void stage_Bimg(unsigned* smu, int img, int tid) {
    unsigned dst = smaddr(smu + U_B);
    const char* src = (const char*)(g_wimg + (size_t)img * 18432);
    #pragma unroll
    for (int t = 0; t < 18; ++t) {
        int o = (tid + t * 256) * 16;
        cpasync16(dst + o, src + o);
    }
    cpcommit();
    cpwait0();
}

// acc[nt][0..3]: rows rw*16+g, rw*16+g+8 x cols cw*64+nt*8+2t, 2t+1
__device__ __forceinline__ void gemm_chunk(const unsigned* __restrict__ smu, int aoff,
                                           float acc[8][4], int rw, int cw, int lane) {
    int g = lane >> 2, t = lane & 3;
    const uint4* A0 = (const uint4*)(smu + aoff + (rw*16 + g) * STR);
    const uint4* A1 = (const uint4*)(smu + aoff + (rw*16 + g + 8) * STR);
    const uint4* B0 = (const uint4*)(smu + U_B + (cw*64 + g) * STR);
    #pragma unroll
    for (int ks = 0; ks < 8; ++ks) {
        uint4 ra0 = A0[ks*4 + t];
        uint4 ra1 = A1[ks*4 + t];
        unsigned Ah[4] = {ra0.x, ra1.x, ra0.y, ra1.y};
        unsigned Al[4] = {ra0.z, ra1.z, ra0.w, ra1.w};
        #pragma unroll
        for (int nt = 0; nt < 8; ++nt) {
            uint4 rb = B0[nt*8*(STR/4) + ks*4 + t];
            mma_bf16(acc[nt], Ah, rb.x, rb.y);
            mma_bf16(acc[nt], Ah, rb.z, rb.w);
            mma_bf16(acc[nt], Al, rb.x, rb.y);
        }
    }
}

__device__ __forceinline__ void zero8(float acc[8][4]) {
    #pragma unroll
    for (int i = 0; i < 8; ++i)
        #pragma unroll
        for (int p = 0; p < 4; ++p) acc[i][p] = 0.f;
}

// silu(acc) -> H smem (frag-ordered)
__device__ __forceinline__ void store_H(unsigned* smu, float acc[8][4],
                                        int rw, int cw, int lane) {
    int g = lane >> 2, t = lane & 3;
    unsigned* h0 = smu + U_H + (rw*16 + g) * STR;
    unsigned* h1 = h0 + 8 * STR;
    #pragma unroll
    for (int nt = 0; nt < 8; ++nt) {
        int j = cw*32 + nt*4 + t;
        st_pair(h0, j, siluf(acc[nt][0]), siluf(acc[nt][1]));
        st_pair(h1, j, siluf(acc[nt][2]), siluf(acc[nt][3]));
    }
}

// LayerNorm across 128 cols (2 col-warps combine via smLN); normalizes acc
__device__ __forceinline__ void ln_frags(float acc[8][4], int rw, int cw, int lane,
                                         const float* __restrict__ gma,
                                         const float* __restrict__ bta,
                                         float2 (*smLN)[2]) {
    int g = lane >> 2, t = lane & 3;
    float s0=0.f, q0=0.f, s1=0.f, q1=0.f;
    #pragma unroll
    for (int nt = 0; nt < 8; ++nt) {
        s0 += acc[nt][0] + acc[nt][1];
        q0 += acc[nt][0]*acc[nt][0] + acc[nt][1]*acc[nt][1];
        s1 += acc[nt][2] + acc[nt][3];
        q1 += acc[nt][2]*acc[nt][2] + acc[nt][3]*acc[nt][3];
    }
    #pragma unroll
    for (int m = 1; m <= 2; m <<= 1) {
        s0 += __shfl_xor_sync(0xffffffffu, s0, m);
        q0 += __shfl_xor_sync(0xffffffffu, q0, m);
        s1 += __shfl_xor_sync(0xffffffffu, s1, m);
        q1 += __shfl_xor_sync(0xffffffffu, q1, m);
    }
    int r0 = rw*16 + g;
    if (t == 0) {
        smLN[r0][cw]     = make_float2(s0, q0);
        smLN[r0 + 8][cw] = make_float2(s1, q1);
    }
    __syncthreads();
    float2 xa = smLN[r0][0], xb = smLN[r0][1];
    float mean0 = (xa.x + xb.x) * 0.0078125f;
    float inv0  = rsqrtf((xa.y + xb.y) * 0.0078125f - mean0*mean0 + 1e-5f);
    xa = smLN[r0 + 8][0]; xb = smLN[r0 + 8][1];
    float mean1 = (xa.x + xb.x) * 0.0078125f;
    float inv1  = rsqrtf((xa.y + xb.y) * 0.0078125f - mean1*mean1 + 1e-5f);
    #pragma unroll
    for (int nt = 0; nt < 8; ++nt) {
        int c = cw*64 + nt*8 + 2*t;
        float ga = __ldg(gma + c), gb = __ldg(gma + c + 1);
        float ba = __ldg(bta + c), bb = __ldg(bta + c + 1);
        acc[nt][0] = (acc[nt][0] - mean0) * inv0 * ga + ba;
        acc[nt][1] = (acc[nt][1] - mean0) * inv0 * gb + bb;
        acc[nt][2] = (acc[nt][2] - mean1) * inv1 * ga + ba;
        acc[nt][3] = (acc[nt][3] - mean1) * inv1 * gb + bb;
    }
}

// ===========================================================================
// prep: zero accumulators + build frag-ordered weight images
// ===========================================================================
__global__ void prep_kernel(const float* __restrict__ w_src,
                            const float* __restrict__ w_tgt,
                            const float* __restrict__ e1c,
                            const float* __restrict__ e2c,
                            const float* __restrict__ e1g,
                            const float* __restrict__ e2g, int nN)
{
    int i = blockIdx.x * blockDim.x + threadIdx.x;
    if (i < 10 * 8192) {
        int img = i >> 13;
        int rem = i & 8191;
        int n = rem >> 6, j = rem & 63;
        int k = 2 * j;
        float v0, v1;
        if (img < 3)       { v0 = e1c[(img*128 + k)*128 + n]; v1 = e1c[(img*128 + k + 1)*128 + n]; }
        else if (img < 6)  { int c = img - 3;
                             v0 = e1g[(c*128 + k)*128 + n];  v1 = e1g[(c*128 + k + 1)*128 + n]; }
        else if (img == 6) { v0 = e2c[k*128 + n];            v1 = e2c[(k + 1)*128 + n]; }
        else if (img == 7) { v0 = e2g[k*128 + n];            v1 = e2g[(k + 1)*128 + n]; }
        else if (img == 8) { v0 = w_src[n*128 + k];          v1 = w_src[n*128 + k + 1]; }
        else               { v0 = w_tgt[n*128 + k];          v1 = w_tgt[n*128 + k + 1]; }
        unsigned hi, lo;
        pack_hl(v0, v1, hi, lo);
        int ks = j >> 3, jj = j & 7, tt = jj & 3, hf = jj >> 2;
        int pos = img * 18432 + n * STR + ks*16 + tt*4 + hf;
        g_wimg[pos]     = hi;
        g_wimg[pos + 2] = lo;
    }
    if (i < nN * D) {
        g_num_src[i] = 0.f; g_den_src[i] = 0.f;
        g_num_tgt[i] = 0.f; g_den_tgt[i] = 0.f;
    }
}

// ===========================================================================
// edge kernel: 64 edges/CTA, 256 threads, mma.sync bf16 hi/lo
// ===========================================================================
__global__ void __launch_bounds__(256) edge_mma_kernel(
    const float* __restrict__ node_feat, const float* __restrict__ edge_feat,
    const float* __restrict__ lgc, const float* __restrict__ lbc,
    const float* __restrict__ lgg, const float* __restrict__ lbg,
    const float* __restrict__ edge_res_w,
    const int* __restrict__ src_idx, const int* __restrict__ tgt_idx,
    float* __restrict__ out_edge, int nE)
{
    extern __shared__ unsigned smu[];
    __shared__ int sidx[64], tidx[64];
    __shared__ float2 smLN[64][2];

    int tid = threadIdx.x;
    int wid = tid >> 5, lane = tid & 31;
    int rw = wid & 3, cw = wid >> 2;
    int e0 = blockIdx.x * 64;

    if (tid < 64) {
        int e = e0 + tid;
        sidx[tid] = (e < nE) ? src_idx[e] : 0;
        tidx[tid] = (e < nE) ? tgt_idx[e] : 0;
    }
    __syncthreads();

    stage_X(smu, U_XE, edge_feat, nullptr, e0, nE, tid);
    stage_X(smu, U_XT, node_feat, tidx, 0, 0, tid);
    stage_X(smu, U_XS, node_feat, sidx, 0, 0, tid);

    #define STAGEB(i) do { __syncthreads(); stage_Bimg(smu, i, tid); __syncthreads(); } while(0)

    float acc[8][4], cn[8][4];

    // ---- core branch ----
    zero8(acc);
    STAGEB(0); gemm_chunk(smu, U_XE, acc, rw, cw, lane);
    STAGEB(1); gemm_chunk(smu, U_XT, acc, rw, cw, lane);
    STAGEB(2); gemm_chunk(smu, U_XS, acc, rw, cw, lane);
    store_H(smu, acc, rw, cw, lane);
    zero8(acc);
    STAGEB(6); gemm_chunk(smu, U_H, acc, rw, cw, lane);
    ln_frags(acc, rw, cw, lane, lgc, lbc, smLN);
    #pragma unroll
    for (int nt = 0; nt < 8; ++nt)
        #pragma unroll
        for (int p = 0; p < 4; ++p) cn[nt][p] = acc[nt][p];

    // ---- gate branch ----
    zero8(acc);
    STAGEB(3); gemm_chunk(smu, U_XE, acc, rw, cw, lane);
    STAGEB(4); gemm_chunk(smu, U_XT, acc, rw, cw, lane);
    STAGEB(5); gemm_chunk(smu, U_XS, acc, rw, cw, lane);
    store_H(smu, acc, rw, cw, lane);
    zero8(acc);
    STAGEB(7); gemm_chunk(smu, U_H, acc, rw, cw, lane);
    ln_frags(acc, rw, cw, lane, lgg, lbg, smLN);
    #pragma unroll
    for (int nt = 0; nt < 8; ++nt)
        #pragma unroll
        for (int p = 0; p < 4; ++p) cn[nt][p] = siluf(cn[nt][p]) * sigmf(acc[nt][p]);

    // attn -> smem [64][stride 129] (reuse XT region)
    {
        float* at = (float*)(smu + U_XT);
        int g = lane >> 2, t = lane & 3;
        int r0 = rw*16 + g;
        #pragma unroll
        for (int nt = 0; nt < 8; ++nt) {
            int c = cw*64 + nt*8 + 2*t;
            at[r0*129 + c]       = cn[nt][0];
            at[r0*129 + c + 1]   = cn[nt][1];
            at[(r0+8)*129 + c]   = cn[nt][2];
            at[(r0+8)*129 + c+1] = cn[nt][3];
        }
    }

    // ---- z GEMMs ----
    zero8(acc);
    STAGEB(8); gemm_chunk(smu, U_XE, acc, rw, cw, lane);
    {
        float* z1 = (float*)(smu + U_XS);
        int g = lane >> 2, t = lane & 3;
        int r0 = rw*16 + g;
        #pragma unroll
        for (int nt = 0; nt < 8; ++nt) {
            int c = cw*64 + nt*8 + 2*t;
            z1[r0*129 + c]       = __expf(acc[nt][0]);
            z1[r0*129 + c + 1]   = __expf(acc[nt][1]);
            z1[(r0+8)*129 + c]   = __expf(acc[nt][2]);
            z1[(r0+8)*129 + c+1] = __expf(acc[nt][3]);
        }
    }
    zero8(acc);
    STAGEB(9); gemm_chunk(smu, U_XE, acc, rw, cw, lane);
    {
        float* z2 = (float*)(smu + U_H);
        int g = lane >> 2, t = lane & 3;
        int r0 = rw*16 + g;
        #pragma unroll
        for (int nt = 0; nt < 8; ++nt) {
            int c = cw*64 + nt*8 + 2*t;
            z2[r0*129 + c]       = __expf(acc[nt][0]);
            z2[r0*129 + c + 1]   = __expf(acc[nt][1]);
            z2[(r0+8)*129 + c]   = __expf(acc[nt][2]);
            z2[(r0+8)*129 + c+1] = __expf(acc[nt][3]);
        }
    }
    __syncthreads();

    // ---- pass C: out_edge = attn + edge_res_w * edge_feat (coalesced) ----
    const float* at = (const float*)(smu + U_XT);
    const float* z1 = (const float*)(smu + U_XS);
    const float* z2 = (const float*)(smu + U_H);
    for (int idx = tid; idx < 64 * 32; idx += 256) {
        int r2 = idx >> 5, q = (idx & 31) << 2;
        int e2 = e0 + r2;
        if (e2 < nE) {
            float4 ef = __ldg((const float4*)(edge_feat + (size_t)e2 * D + q));
            float4 rwv = __ldg((const float4*)(edge_res_w + q));
            const float* ap = at + r2*129 + q;
            float4 o = {ap[0] + rwv.x*ef.x, ap[1] + rwv.y*ef.y,
                        ap[2] + rwv.z*ef.z, ap[3] + rwv.w*ef.w};
            *(float4*)(out_edge + (size_t)e2 * D + q) = o;
        }
    }

    // ---- pass D: softmax num/den atomics ----
    for (int idx = tid; idx < 64 * 32; idx += 256) {
        int r2 = idx >> 5, q = (idx & 31) << 2;
        int e2 = e0 + r2;
        if (e2 < nE) {
            int ns = sidx[r2], ntg = tidx[r2];
            const float* ap = at + r2*129 + q;
            const float* p1 = z1 + r2*129 + q;
            const float* p2 = z2 + r2*129 + q;
            red4(g_den_src + (size_t)ns * D + q, p1[0], p1[1], p1[2], p1[3]);
            red4(g_num_src + (size_t)ns * D + q,
                 p1[0]*ap[0], p1[1]*ap[1], p1[2]*ap[2], p1[3]*ap[3]);
            red4(g_den_tgt + (size_t)ntg * D + q, p2[0], p2[1], p2[2], p2[3]);
            red4(g_num_tgt + (size_t)ntg * D + q,
                 p2[0]*ap[0], p2[1]*ap[1], p2[2]*ap[2], p2[3]*ap[3]);
        }
    }
    #undef STAGEB
}

// ===========================================================================
// node path (R3 f32x2) — unchanged
// ===========================================================================
__device__ __forceinline__ u64_t pack2(float x) {
    u64_t r; asm("mov.b64 %0,{%1,%1};" : "=l"(r) : "f"(x)); return r;
}
__device__ __forceinline__ void unpack2(u64_t v, float& lo, float& hi) {
    asm("mov.b64 {%0,%1},%2;" : "=f"(lo), "=f"(hi) : "l"(v));
}
__device__ __forceinline__ void fma2(u64_t& d, u64_t a, u64_t b) {
    asm("fma.rn.f32x2 %0,%1,%2,%0;" : "+l"(d) : "l"(a), "l"(b));
}
__device__ __forceinline__ float f4get(const float4& v, int i) {
    switch (i) { case 0: return v.x; case 1: return v.y; case 2: return v.z; default: return v.w; }
}

__device__ __forceinline__ void gemm_tile(
    const float* __restrict__ Xsm, int xld, const float* __restrict__ gW,
    float* __restrict__ Wsm, int Ktot, u64_t acc[4][4], int r0, int cb, int tid)
{
    const int nb = Ktot >> 6;
    const int srow = tid >> 5, scol = (tid & 31) << 2;
    #pragma unroll
    for (int t = 0; t < 8; ++t)
        cpasync16(smaddr(Wsm + (srow + t * 8) * D + scol),
                  gW + (size_t)(srow + t * 8) * D + scol);
    cpcommit(); cpwait0(); __syncthreads();

    for (int b = 0; b < nb; ++b) {
        const float* cur = Wsm + (b & 1) * WBUF;
        if (b + 1 < nb) {
            const float* src = gW + (size_t)(b + 1) * 64 * D;
            float* dst = Wsm + ((b + 1) & 1) * WBUF;
            #pragma unroll
            for (int t = 0; t < 8; ++t)
                cpasync16(smaddr(dst + (srow + t * 8) * D + scol),
                          src + (size_t)(srow + t * 8) * D + scol);
            cpcommit();
        }
        const float* x0 = Xsm + (r0 + 0) * xld + (b << 6);
        const float* x1 = Xsm + (r0 + 1) * xld + (b << 6);
        const float* x2 = Xsm + (r0 + 2) * xld + (b << 6);
        const float* x3 = Xsm + (r0 + 3) * xld + (b << 6);
        #pragma unroll 2
        for (int k = 0; k < 64; k += 4) {
            float4 xr0 = *(const float4*)(x0 + k);
            float4 xr1 = *(const float4*)(x1 + k);
            float4 xr2 = *(const float4*)(x2 + k);
            float4 xr3 = *(const float4*)(x3 + k);
            #pragma unroll
            for (int kk = 0; kk < 4; ++kk) {
                ulonglong2 wA = *(const ulonglong2*)(cur + (k + kk) * D + cb);
                ulonglong2 wB = *(const ulonglong2*)(cur + (k + kk) * D + cb + 32);
                u64_t xa = pack2(f4get(xr0, kk)), xb = pack2(f4get(xr1, kk));
                u64_t xc = pack2(f4get(xr2, kk)), xd = pack2(f4get(xr3, kk));
                fma2(acc[0][0], xa, wA.x); fma2(acc[0][1], xa, wA.y);
                fma2(acc[0][2], xa, wB.x); fma2(acc[0][3], xa, wB.y);
                fma2(acc[1][0], xb, wA.x); fma2(acc[1][1], xb, wA.y);
                fma2(acc[1][2], xb, wB.x); fma2(acc[1][3], xb, wB.y);
                fma2(acc[2][0], xc, wA.x); fma2(acc[2][1], xc, wA.y);
                fma2(acc[2][2], xc, wB.x); fma2(acc[2][3], xc, wB.y);
                fma2(acc[3][0], xd, wA.x); fma2(acc[3][1], xd, wA.y);
                fma2(acc[3][2], xd, wB.x); fma2(acc[3][3], xd, wB.y);
            }
        }
        cpwait0(); __syncthreads();
    }
}

__device__ __forceinline__ void zero_acc(u64_t acc[4][4]) {
    #pragma unroll
    for (int i = 0; i < 4; ++i)
        #pragma unroll
        for (int p = 0; p < 4; ++p) acc[i][p] = 0ULL;
}
__device__ __forceinline__ void acc_to_f(u64_t acc[4][4], float a[4][8]) {
    #pragma unroll
    for (int i = 0; i < 4; ++i)
        #pragma unroll
        for (int p = 0; p < 4; ++p) unpack2(acc[i][p], a[i][2*p], a[i][2*p+1]);
}

__device__ __forceinline__ void layernorm_rows(float a[4][8],
    const float* __restrict__ g, const float* __restrict__ b,
    int cb, int col_warp, int r0, int lane, float2 (*smLN)[2])
{
    float4 g0 = *(const float4*)(g + cb), g1 = *(const float4*)(g + cb + 32);
    float4 b0 = *(const float4*)(b + cb), b1 = *(const float4*)(b + cb + 32);
    float gv[8] = {g0.x, g0.y, g0.z, g0.w, g1.x, g1.y, g1.z, g1.w};
    float bv[8] = {b0.x, b0.y, b0.z, b0.w, b1.x, b1.y, b1.z, b1.w};
    float s1[4], s2[4];
    #pragma unroll
    for (int i = 0; i < 4; ++i) {
        float s = 0.f, q = 0.f;
        #pragma unroll
        for (int j = 0; j < 8; ++j) { s += a[i][j]; q += a[i][j] * a[i][j]; }
        #pragma unroll
        for (int m = 1; m <= 4; m <<= 1) {
            s += __shfl_xor_sync(0xffffffffu, s, m);
            q += __shfl_xor_sync(0xffffffffu, q, m);
        }
        s1[i] = s; s2[i] = q;
    }
    if ((lane & 7) == 0) {
        #pragma unroll
        for (int i = 0; i < 4; ++i) smLN[r0 + i][col_warp] = make_float2(s1[i], s2[i]);
    }
    __syncthreads();
    #pragma unroll
    for (int i = 0; i < 4; ++i) {
        float2 pa = smLN[r0 + i][0], pb = smLN[r0 + i][1];
        float mean = (pa.x + pb.x) * 0.0078125f;
        float inv = rsqrtf((pa.y + pb.y) * 0.0078125f - mean * mean + 1e-5f);
        #pragma unroll
        for (int j = 0; j < 8; ++j) a[i][j] = (a[i][j] - mean) * inv * gv[j] + bv[j];
    }
}

__global__ void __launch_bounds__(NTHREADS) node_kernel(
    const float* __restrict__ node_feat,
    const float* __restrict__ w1c, const float* __restrict__ w2c,
    const float* __restrict__ w1g, const float* __restrict__ w2g,
    const float* __restrict__ lgc, const float* __restrict__ lbc,
    const float* __restrict__ lgg, const float* __restrict__ lbg,
    const float* __restrict__ node_res_w,
    float* __restrict__ out_node, int nN)
{
    extern __shared__ float sm[];
    float* Xsm = sm;
    float* Hsm = sm + TILE * XLD;
    float* Wsm = Hsm + TILE * HLD;
    __shared__ float2 smLN[TILE][2];

    int tid = threadIdx.x;
    int n0 = blockIdx.x * TILE;

    for (int idx = tid; idx < TILE * 96; idx += NTHREADS) {
        int r = idx / 96, p = idx % 96;
        int n = n0 + r;
        float4 v = {0.f, 0.f, 0.f, 0.f};
        if (n < nN) {
            if (p < 32) {
                v = *(const float4*)(node_feat + (size_t)n * D + p * 4);
            } else if (p < 64) {
                int o = (p - 32) * 4;
                float4 nu = *(const float4*)(g_num_tgt + (size_t)n * D + o);
                float4 de = *(const float4*)(g_den_tgt + (size_t)n * D + o);
                v.x = nu.x / (de.x + 1e-16f); v.y = nu.y / (de.y + 1e-16f);
                v.z = nu.z / (de.z + 1e-16f); v.w = nu.w / (de.w + 1e-16f);
            } else {
                int o = (p - 64) * 4;
                float4 nu = *(const float4*)(g_num_src + (size_t)n * D + o);
                float4 de = *(const float4*)(g_den_src + (size_t)n * D + o);
                v.x = nu.x / (de.x + 1e-16f); v.y = nu.y / (de.y + 1e-16f);
                v.z = nu.z / (de.z + 1e-16f); v.w = nu.w / (de.w + 1e-16f);
            }
        }
        *(float4*)(Xsm + r * XLD + p * 4) = v;
    }

    int wid = tid >> 5, lane = tid & 31;
    int row_warp = wid >> 1, col_warp = wid & 1;
    int ty = lane >> 3, tx = lane & 7;
    int r0 = row_warp * 16 + ty * 4;
    int cb = col_warp * 64 + tx * 4;

    u64_t acc[4][4];
    float a[4][8], attn[4][8];

    zero_acc(acc);
    gemm_tile(Xsm, XLD, w1c, Wsm, 384, acc, r0, cb, tid);
    acc_to_f(acc, a);
    #pragma unroll
    for (int i = 0; i < 4; ++i) {
        float4 h0 = {siluf(a[i][0]), siluf(a[i][1]), siluf(a[i][2]), siluf(a[i][3])};
        float4 h1 = {siluf(a[i][4]), siluf(a[i][5]), siluf(a[i][6]), siluf(a[i][7])};
        *(float4*)(Hsm + (r0 + i) * HLD + cb)      = h0;
        *(float4*)(Hsm + (r0 + i) * HLD + cb + 32) = h1;
    }
    zero_acc(acc);
    gemm_tile(Hsm, HLD, w2c, Wsm, 128, acc, r0, cb, tid);
    acc_to_f(acc, a);
    layernorm_rows(a, lgc, lbc, cb, col_warp, r0, lane, smLN);
    #pragma unroll
    for (int i = 0; i < 4; ++i)
        #pragma unroll
        for (int j = 0; j < 8; ++j) attn[i][j] = a[i][j];

    zero_acc(acc);
    gemm_tile(Xsm, XLD, w1g, Wsm, 384, acc, r0, cb, tid);
    acc_to_f(acc, a);
    #pragma unroll
    for (int i = 0; i < 4; ++i) {
        float4 h0 = {siluf(a[i][0]), siluf(a[i][1]), siluf(a[i][2]), siluf(a[i][3])};
        float4 h1 = {siluf(a[i][4]), siluf(a[i][5]), siluf(a[i][6]), siluf(a[i][7])};
        *(float4*)(Hsm + (r0 + i) * HLD + cb)      = h0;
        *(float4*)(Hsm + (r0 + i) * HLD + cb + 32) = h1;
    }
    zero_acc(acc);
    gemm_tile(Hsm, HLD, w2g, Wsm, 128, acc, r0, cb, tid);
    acc_to_f(acc, a);
    layernorm_rows(a, lgg, lbg, cb, col_warp, r0, lane, smLN);
    #pragma unroll
    for (int i = 0; i < 4; ++i)
        #pragma unroll
        for (int j = 0; j < 8; ++j)
            attn[i][j] = siluf(attn[i][j]) * sigmf(a[i][j]);

    float4 rw0 = *(const float4*)(node_res_w + cb);
    float4 rw1 = *(const float4*)(node_res_w + cb + 32);
    float rwv[8] = {rw0.x, rw0.y, rw0.z, rw0.w, rw1.x, rw1.y, rw1.z, rw1.w};
    #pragma unroll
    for (int i = 0; i < 4; ++i) {
        int n = n0 + r0 + i;
        if (n < nN) {
            const float* nfA = Xsm + (r0 + i) * XLD + cb;
            const float* nfB = nfA + 32;
            float4 o0 = {attn[i][0] + rwv[0]*nfA[0], attn[i][1] + rwv[1]*nfA[1],
                         attn[i][2] + rwv[2]*nfA[2], attn[i][3] + rwv[3]*nfA[3]};
            float4 o1 = {attn[i][4] + rwv[4]*nfB[0], attn[i][5] + rwv[5]*nfB[1],
                         attn[i][6] + rwv[6]*nfB[2], attn[i][7] + rwv[7]*nfB[3]};
            *(float4*)(out_node + (size_t)n * D + cb)      = o0;
            *(float4*)(out_node + (size_t)n * D + cb + 32) = o1;
        }
    }
}

// ---------------------------------------------------------------------------
extern "C" void kernel_launch(void* const* d_in, const int* in_sizes, int n_in,
                              void* d_out, int out_size)
{
    const float* node_feat = (const float*)d_in[0];
    const float* edge_feat = (const float*)d_in[1];
    const float* w_src     = (const float*)d_in[2];
    const float* w_tgt     = (const float*)d_in[3];
    const float* e_core_w1 = (const float*)d_in[4];
    const float* e_core_w2 = (const float*)d_in[5];
    const float* e_gate_w1 = (const float*)d_in[6];
    const float* e_gate_w2 = (const float*)d_in[7];
    const float* e_ln_cg   = (const float*)d_in[8];
    const float* e_ln_cb   = (const float*)d_in[9];
    const float* e_ln_gg   = (const float*)d_in[10];
    const float* e_ln_gb   = (const float*)d_in[11];
    const float* n_core_w1 = (const float*)d_in[12];
    const float* n_core_w2 = (const float*)d_in[13];
    const float* n_gate_w1 = (const float*)d_in[14];
    const float* n_gate_w2 = (const float*)d_in[15];
    const float* n_ln_cg   = (const float*)d_in[16];
    const float* n_ln_cb   = (const float*)d_in[17];
    const float* n_ln_gg   = (const float*)d_in[18];
    const float* n_ln_gb   = (const float*)d_in[19];
    const float* node_res_w= (const float*)d_in[20];
    const float* edge_res_w= (const float*)d_in[21];
    const int*   src_idx   = (const int*)d_in[22];
    const int*   tgt_idx   = (const int*)d_in[23];

    int nN = in_sizes[0] / D;
    int nE = in_sizes[1] / D;

    float* out_node = (float*)d_out;
    float* out_edge = out_node + (size_t)nN * D;

    cudaFuncSetAttribute(edge_mma_kernel, cudaFuncAttributeMaxDynamicSharedMemorySize, E_DYN);
    cudaFuncSetAttribute(node_kernel, cudaFuncAttributeMaxDynamicSharedMemorySize, SMEM_BYTES);

    prep_kernel<<<(nN * D + 255) / 256, 256>>>(w_src, w_tgt,
        e_core_w1, e_core_w2, e_gate_w1, e_gate_w2, nN);

    edge_mma_kernel<<<(nE + 63) / 64, 256, E_DYN>>>(
        node_feat, edge_feat,
        e_ln_cg, e_ln_cb, e_ln_gg, e_ln_gb,
        edge_res_w, src_idx, tgt_idx, out_edge, nE);

    node_kernel<<<(nN + TILE - 1) / TILE, NTHREADS, SMEM_BYTES>>>(
        node_feat,
        n_core_w1, n_core_w2, n_gate_w1, n_gate_w2,
        n_ln_cg, n_ln_cb, n_ln_gg, n_ln_gb,
        node_res_w, out_node, nN);
}

// round 12
// speedup vs baseline: 1.4698x; 1.0034x over previous
#include <cuda_runtime.h>
#include <cuda_bf16.h>

// ===========================================================================
// Graph attention layer. R6: edge path on mma.sync bf16 hi/lo (3-term);
// node path keeps R3 f32x2.
//   out = concat(attn_node [N,128], attn_edge [E,128])
// ===========================================================================

#define D        128
#define NMAX     10000

// ---- node path (R3) ----
#define TILE     64
#define XLD      388
#define HLD      132
#define NTHREADS 256
#define WBUF     (64 * D)
#define SMEM_BYTES ((TILE*XLD + TILE*HLD + 2*WBUF) * 4)

__device__ __align__(16) float g_num_src[NMAX * D];
__device__ __align__(16) float g_den_src[NMAX * D];
__device__ __align__(16) float g_num_tgt[NMAX * D];
__device__ __align__(16) float g_den_tgt[NMAX * D];
// fragment-ordered bf16 hi/lo weight images, 10 x [128 n][144 u32]:
// 0-2 e_core_w1 k-chunks, 3-5 e_gate_w1 k-chunks, 6 e_core_w2, 7 e_gate_w2,
// 8 w_src (as B[k][n]=w_src[n][k]), 9 w_tgt
__device__ __align__(16) unsigned g_wimg[10 * 18432];

typedef unsigned long long u64_t;

// ---------- common helpers ----------
__device__ __forceinline__ float siluf(float x)  { return x / (1.f + __expf(-x)); }
__device__ __forceinline__ float sigmf(float x)  { return 1.f / (1.f + __expf(-x)); }
__device__ __forceinline__ void red4(float* a, float x, float y, float z, float w) {
    asm volatile("red.global.add.v4.f32 [%0],{%1,%2,%3,%4};"
                 :: "l"(a), "f"(x), "f"(y), "f"(z), "f"(w) : "memory");
}
__device__ __forceinline__ unsigned smaddr(const void* p) {
    return (unsigned)__cvta_generic_to_shared(p);
}
__device__ __forceinline__ void cpasync16(unsigned dst, const void* src) {
    asm volatile("cp.async.cg.shared.global [%0], [%1], 16;" :: "r"(dst), "l"(src) : "memory");
}
__device__ __forceinline__ void cpcommit() { asm volatile("cp.async.commit_group;" ::: "memory"); }
__device__ __forceinline__ void cpwait0()  { asm volatile("cp.async.wait_group 0;" ::: "memory"); }

// pack (x0,x1) into bf16x2 hi and residual lo
__device__ __forceinline__ void pack_hl(float x0, float x1, unsigned& hi, unsigned& lo) {
    __nv_bfloat16 h0 = __float2bfloat16(x0), h1 = __float2bfloat16(x1);
    __nv_bfloat16 l0 = __float2bfloat16(x0 - __bfloat162float(h0));
    __nv_bfloat16 l1 = __float2bfloat16(x1 - __bfloat162float(h1));
    hi = (unsigned)__bfloat16_as_ushort(h0) | ((unsigned)__bfloat16_as_ushort(h1) << 16);
    lo = (unsigned)__bfloat16_as_ushort(l0) | ((unsigned)__bfloat16_as_ushort(l1) << 16);
}

// mma.sync m16n8k16 bf16: D += A*B
__device__ __forceinline__ void mma_bf16(float d[4], const unsigned a[4],
                                         unsigned b0, unsigned b1) {
    asm volatile("mma.sync.aligned.m16n8k16.row.col.f32.bf16.bf16.f32 "
        "{%0,%1,%2,%3},{%4,%5,%6,%7},{%8,%9},{%0,%1,%2,%3};"
        : "+f"(d[0]), "+f"(d[1]), "+f"(d[2]), "+f"(d[3])
        : "r"(a[0]), "r"(a[1]), "r"(a[2]), "r"(a[3]), "r"(b0), "r"(b1));
}

// ---- edge smem layout (u32 offsets). Row stride = 144 u32.
// Per row, per (ks,t): u32s [hi(kpair t), hi(kpair t+4), lo(t), lo(t+4)]
// at position ks*16 + t*4. kpair j -> ks=j>>3, tt=(j&7)&3, hf=(j&7)>>2:
// hi at ks*16+tt*4+hf, lo at +2.
#define STR   144
#define U_XE  0
#define U_XT  9216
#define U_XS  18432
#define U_H   27648
#define U_B   36864
#define E_UTOT 55296
#define E_DYN  (E_UTOT * 4)

__device__ __forceinline__ void st_pair(unsigned* rowbase, int j, float x0, float x1) {
    int ks = j >> 3, jj = j & 7, tt = jj & 3, hf = jj >> 2;
    unsigned hi, lo;
    pack_hl(x0, x1, hi, lo);
    rowbase[ks*16 + tt*4 + hf]     = hi;
    rowbase[ks*16 + tt*4 + hf + 2] = lo;
}

// stage a 64x128 fp32 block (optionally gathered rows) into frag-ordered smem
__device__ __forceinline__ void stage_X(unsigned* smu, int off, const float* base,
                                        const int* ridx, int e0, int nE, int tid) {
    int r = tid >> 2, part = tid & 3;
    long row = ridx ? (long)ridx[r] : (long)(e0 + r);
    bool ok = ridx ? true : ((e0 + r) < nE);
    const float* p = base + row * D + part * 32;
    unsigned* rb = smu + off + r * STR;
    #pragma unroll
    for (int q = 0; q < 8; ++q) {
        float4 v = ok ? __ldg((const float4*)(p + q * 4)) : make_float4(0.f,0.f,0.f,0.f);
        int j0 = part * 16 + q * 2;
        st_pair(rb, j0,     v.x, v.y);
        st_pair(rb, j0 + 1, v.z, v.w);
    }
}

// copy one weight image (73728 B) into B smem
__device__ __forceinline__ void stage_Bimg(unsigned* smu, int img, int tid) {
    unsigned dst = smaddr(smu + U_B);
    const char* src = (const char*)(g_wimg + (size_t)img * 18432);
    #pragma unroll
    for (int t = 0; t < 18; ++t) {
        int o = (tid + t * 256) * 16;
        cpasync16(dst + o, src + o);
    }
    cpcommit();
    cpwait0();
}

// acc[nt][0..3]: rows rw*16+g, rw*16+g+8 x cols cw*64+nt*8+2t, 2t+1
__device__ __forceinline__ void gemm_chunk(const unsigned* __restrict__ smu, int aoff,
                                           float acc[8][4], int rw, int cw, int lane) {
    int g = lane >> 2, t = lane & 3;
    const uint4* A0 = (const uint4*)(smu + aoff + (rw*16 + g) * STR);
    const uint4* A1 = (const uint4*)(smu + aoff + (rw*16 + g + 8) * STR);
    const uint4* B0 = (const uint4*)(smu + U_B + (cw*64 + g) * STR);
    #pragma unroll
    for (int ks = 0; ks < 8; ++ks) {
        uint4 ra0 = A0[ks*4 + t];
        uint4 ra1 = A1[ks*4 + t];
        unsigned Ah[4] = {ra0.x, ra1.x, ra0.y, ra1.y};
        unsigned Al[4] = {ra0.z, ra1.z, ra0.w, ra1.w};
        #pragma unroll
        for (int nt = 0; nt < 8; ++nt) {
            uint4 rb = B0[nt*8*(STR/4) + ks*4 + t];
            mma_bf16(acc[nt], Ah, rb.x, rb.y);
            mma_bf16(acc[nt], Ah, rb.z, rb.w);
            mma_bf16(acc[nt], Al, rb.x, rb.y);
        }
    }
}

__device__ __forceinline__ void zero8(float acc[8][4]) {
    #pragma unroll
    for (int i = 0; i < 8; ++i)
        #pragma unroll
        for (int p = 0; p < 4; ++p) acc[i][p] = 0.f;
}

// silu(acc) -> H smem (frag-ordered)
__device__ __forceinline__ void store_H(unsigned* smu, float acc[8][4],
                                        int rw, int cw, int lane) {
    int g = lane >> 2, t = lane & 3;
    unsigned* h0 = smu + U_H + (rw*16 + g) * STR;
    unsigned* h1 = h0 + 8 * STR;
    #pragma unroll
    for (int nt = 0; nt < 8; ++nt) {
        int j = cw*32 + nt*4 + t;
        st_pair(h0, j, siluf(acc[nt][0]), siluf(acc[nt][1]));
        st_pair(h1, j, siluf(acc[nt][2]), siluf(acc[nt][3]));
    }
}

// LayerNorm across 128 cols (2 col-warps combine via smLN); normalizes acc
__device__ __forceinline__ void ln_frags(float acc[8][4], int rw, int cw, int lane,
                                         const float* __restrict__ gma,
                                         const float* __restrict__ bta,
                                         float2 (*smLN)[2]) {
    int g = lane >> 2, t = lane & 3;
    float s0=0.f, q0=0.f, s1=0.f, q1=0.f;
    #pragma unroll
    for (int nt = 0; nt < 8; ++nt) {
        s0 += acc[nt][0] + acc[nt][1];
        q0 += acc[nt][0]*acc[nt][0] + acc[nt][1]*acc[nt][1];
        s1 += acc[nt][2] + acc[nt][3];
        q1 += acc[nt][2]*acc[nt][2] + acc[nt][3]*acc[nt][3];
    }
    #pragma unroll
    for (int m = 1; m <= 2; m <<= 1) {
        s0 += __shfl_xor_sync(0xffffffffu, s0, m);
        q0 += __shfl_xor_sync(0xffffffffu, q0, m);
        s1 += __shfl_xor_sync(0xffffffffu, s1, m);
        q1 += __shfl_xor_sync(0xffffffffu, q1, m);
    }
    int r0 = rw*16 + g;
    if (t == 0) {
        smLN[r0][cw]     = make_float2(s0, q0);
        smLN[r0 + 8][cw] = make_float2(s1, q1);
    }
    __syncthreads();
    float2 xa = smLN[r0][0], xb = smLN[r0][1];
    float mean0 = (xa.x + xb.x) * 0.0078125f;
    float inv0  = rsqrtf((xa.y + xb.y) * 0.0078125f - mean0*mean0 + 1e-5f);
    xa = smLN[r0 + 8][0]; xb = smLN[r0 + 8][1];
    float mean1 = (xa.x + xb.x) * 0.0078125f;
    float inv1  = rsqrtf((xa.y + xb.y) * 0.0078125f - mean1*mean1 + 1e-5f);
    #pragma unroll
    for (int nt = 0; nt < 8; ++nt) {
        int c = cw*64 + nt*8 + 2*t;
        float ga = __ldg(gma + c), gb = __ldg(gma + c + 1);
        float ba = __ldg(bta + c), bb = __ldg(bta + c + 1);
        acc[nt][0] = (acc[nt][0] - mean0) * inv0 * ga + ba;
        acc[nt][1] = (acc[nt][1] - mean0) * inv0 * gb + bb;
        acc[nt][2] = (acc[nt][2] - mean1) * inv1 * ga + ba;
        acc[nt][3] = (acc[nt][3] - mean1) * inv1 * gb + bb;
    }
}

// ===========================================================================
// prep: zero accumulators + build frag-ordered weight images
// ===========================================================================
__global__ void prep_kernel(const float* __restrict__ w_src,
                            const float* __restrict__ w_tgt,
                            const float* __restrict__ e1c,
                            const float* __restrict__ e2c,
                            const float* __restrict__ e1g,
                            const float* __restrict__ e2g, int nN)
{
    int i = blockIdx.x * blockDim.x + threadIdx.x;
    if (i < 10 * 8192) {
        int img = i >> 13;
        int rem = i & 8191;
        int n = rem >> 6, j = rem & 63;
        int k = 2 * j;
        float v0, v1;
        if (img < 3)       { v0 = e1c[(img*128 + k)*128 + n]; v1 = e1c[(img*128 + k + 1)*128 + n]; }
        else if (img < 6)  { int c = img - 3;
                             v0 = e1g[(c*128 + k)*128 + n];  v1 = e1g[(c*128 + k + 1)*128 + n]; }
        else if (img == 6) { v0 = e2c[k*128 + n];            v1 = e2c[(k + 1)*128 + n]; }
        else if (img == 7) { v0 = e2g[k*128 + n];            v1 = e2g[(k + 1)*128 + n]; }
        else if (img == 8) { v0 = w_src[n*128 + k];          v1 = w_src[n*128 + k + 1]; }
        else               { v0 = w_tgt[n*128 + k];          v1 = w_tgt[n*128 + k + 1]; }
        unsigned hi, lo;
        pack_hl(v0, v1, hi, lo);
        int ks = j >> 3, jj = j & 7, tt = jj & 3, hf = jj >> 2;
        int pos = img * 18432 + n * STR + ks*16 + tt*4 + hf;
        g_wimg[pos]     = hi;
        g_wimg[pos + 2] = lo;
    }
    if (i < nN * D) {
        g_num_src[i] = 0.f; g_den_src[i] = 0.f;
        g_num_tgt[i] = 0.f; g_den_tgt[i] = 0.f;
    }
}

// ===========================================================================
// edge kernel: 64 edges/CTA, 256 threads, mma.sync bf16 hi/lo
// ===========================================================================
__global__ void __launch_bounds__(256) edge_mma_kernel(
    const float* __restrict__ node_feat, const float* __restrict__ edge_feat,
    const float* __restrict__ lgc, const float* __restrict__ lbc,
    const float* __restrict__ lgg, const float* __restrict__ lbg,
    const float* __restrict__ edge_res_w,
    const int* __restrict__ src_idx, const int* __restrict__ tgt_idx,
    float* __restrict__ out_edge, int nE)
{
    extern __shared__ unsigned smu[];
    __shared__ int sidx[64], tidx[64];
    __shared__ float2 smLN[64][2];

    int tid = threadIdx.x;
    int wid = tid >> 5, lane = tid & 31;
    int rw = wid & 3, cw = wid >> 2;
    int e0 = blockIdx.x * 64;

    if (tid < 64) {
        int e = e0 + tid;
        sidx[tid] = (e < nE) ? src_idx[e] : 0;
        tidx[tid] = (e < nE) ? tgt_idx[e] : 0;
    }
    __syncthreads();

    stage_X(smu, U_XE, edge_feat, nullptr, e0, nE, tid);
    stage_X(smu, U_XT, node_feat, tidx, 0, 0, tid);
    stage_X(smu, U_XS, node_feat, sidx, 0, 0, tid);

    #define STAGEB(i) do { __syncthreads(); stage_Bimg(smu, i, tid); __syncthreads(); } while(0)

    float acc[8][4], cn[8][4];

    // ---- core branch ----
    zero8(acc);
    STAGEB(0); gemm_chunk(smu, U_XE, acc, rw, cw, lane);
    STAGEB(1); gemm_chunk(smu, U_XT, acc, rw, cw, lane);
    STAGEB(2); gemm_chunk(smu, U_XS, acc, rw, cw, lane);
    store_H(smu, acc, rw, cw, lane);
    zero8(acc);
    STAGEB(6); gemm_chunk(smu, U_H, acc, rw, cw, lane);
    ln_frags(acc, rw, cw, lane, lgc, lbc, smLN);
    #pragma unroll
    for (int nt = 0; nt < 8; ++nt)
        #pragma unroll
        for (int p = 0; p < 4; ++p) cn[nt][p] = acc[nt][p];

    // ---- gate branch ----
    zero8(acc);
    STAGEB(3); gemm_chunk(smu, U_XE, acc, rw, cw, lane);
    STAGEB(4); gemm_chunk(smu, U_XT, acc, rw, cw, lane);
    STAGEB(5); gemm_chunk(smu, U_XS, acc, rw, cw, lane);
    store_H(smu, acc, rw, cw, lane);
    zero8(acc);
    STAGEB(7); gemm_chunk(smu, U_H, acc, rw, cw, lane);
    ln_frags(acc, rw, cw, lane, lgg, lbg, smLN);
    #pragma unroll
    for (int nt = 0; nt < 8; ++nt)
        #pragma unroll
        for (int p = 0; p < 4; ++p) cn[nt][p] = siluf(cn[nt][p]) * sigmf(acc[nt][p]);

    // attn -> smem [64][stride 129] (reuse XT region)
    {
        float* at = (float*)(smu + U_XT);
        int g = lane >> 2, t = lane & 3;
        int r0 = rw*16 + g;
        #pragma unroll
        for (int nt = 0; nt < 8; ++nt) {
            int c = cw*64 + nt*8 + 2*t;
            at[r0*129 + c]       = cn[nt][0];
            at[r0*129 + c + 1]   = cn[nt][1];
            at[(r0+8)*129 + c]   = cn[nt][2];
            at[(r0+8)*129 + c+1] = cn[nt][3];
        }
    }

    // ---- z GEMMs ----
    zero8(acc);
    STAGEB(8); gemm_chunk(smu, U_XE, acc, rw, cw, lane);
    {
        float* z1 = (float*)(smu + U_XS);
        int g = lane >> 2, t = lane & 3;
        int r0 = rw*16 + g;
        #pragma unroll
        for (int nt = 0; nt < 8; ++nt) {
            int c = cw*64 + nt*8 + 2*t;
            z1[r0*129 + c]       = __expf(acc[nt][0]);
            z1[r0*129 + c + 1]   = __expf(acc[nt][1]);
            z1[(r0+8)*129 + c]   = __expf(acc[nt][2]);
            z1[(r0+8)*129 + c+1] = __expf(acc[nt][3]);
        }
    }
    zero8(acc);
    STAGEB(9); gemm_chunk(smu, U_XE, acc, rw, cw, lane);
    {
        float* z2 = (float*)(smu + U_H);
        int g = lane >> 2, t = lane & 3;
        int r0 = rw*16 + g;
        #pragma unroll
        for (int nt = 0; nt < 8; ++nt) {
            int c = cw*64 + nt*8 + 2*t;
            z2[r0*129 + c]       = __expf(acc[nt][0]);
            z2[r0*129 + c + 1]   = __expf(acc[nt][1]);
            z2[(r0+8)*129 + c]   = __expf(acc[nt][2]);
            z2[(r0+8)*129 + c+1] = __expf(acc[nt][3]);
        }
    }
    __syncthreads();

    // ---- pass C: out_edge = attn + edge_res_w * edge_feat (coalesced) ----
    const float* at = (const float*)(smu + U_XT);
    const float* z1 = (const float*)(smu + U_XS);
    const float* z2 = (const float*)(smu + U_H);
    for (int idx = tid; idx < 64 * 32; idx += 256) {
        int r2 = idx >> 5, q = (idx & 31) << 2;
        int e2 = e0 + r2;
        if (e2 < nE) {
            float4 ef = __ldg((const float4*)(edge_feat + (size_t)e2 * D + q));
            float4 rwv = __ldg((const float4*)(edge_res_w + q));
            const float* ap = at + r2*129 + q;
            float4 o = {ap[0] + rwv.x*ef.x, ap[1] + rwv.y*ef.y,
                        ap[2] + rwv.z*ef.z, ap[3] + rwv.w*ef.w};
            *(float4*)(out_edge + (size_t)e2 * D + q) = o;
        }
    }

    // ---- pass D: softmax num/den atomics ----
    for (int idx = tid; idx < 64 * 32; idx += 256) {
        int r2 = idx >> 5, q = (idx & 31) << 2;
        int e2 = e0 + r2;
        if (e2 < nE) {
            int ns = sidx[r2], ntg = tidx[r2];
            const float* ap = at + r2*129 + q;
            const float* p1 = z1 + r2*129 + q;
            const float* p2 = z2 + r2*129 + q;
            red4(g_den_src + (size_t)ns * D + q, p1[0], p1[1], p1[2], p1[3]);
            red4(g_num_src + (size_t)ns * D + q,
                 p1[0]*ap[0], p1[1]*ap[1], p1[2]*ap[2], p1[3]*ap[3]);
            red4(g_den_tgt + (size_t)ntg * D + q, p2[0], p2[1], p2[2], p2[3]);
            red4(g_num_tgt + (size_t)ntg * D + q,
                 p2[0]*ap[0], p2[1]*ap[1], p2[2]*ap[2], p2[3]*ap[3]);
        }
    }
    #undef STAGEB
}

// ===========================================================================
// node path (R3 f32x2) — unchanged
// ===========================================================================
__device__ __forceinline__ u64_t pack2(float x) {
    u64_t r; asm("mov.b64 %0,{%1,%1};" : "=l"(r) : "f"(x)); return r;
}
__device__ __forceinline__ void unpack2(u64_t v, float& lo, float& hi) {
    asm("mov.b64 {%0,%1},%2;" : "=f"(lo), "=f"(hi) : "l"(v));
}
__device__ __forceinline__ void fma2(u64_t& d, u64_t a, u64_t b) {
    asm("fma.rn.f32x2 %0,%1,%2,%0;" : "+l"(d) : "l"(a), "l"(b));
}
__device__ __forceinline__ float f4get(const float4& v, int i) {
    switch (i) { case 0: return v.x; case 1: return v.y; case 2: return v.z; default: return v.w; }
}

__device__ __forceinline__ void gemm_tile(
    const float* __restrict__ Xsm, int xld, const float* __restrict__ gW,
    float* __restrict__ Wsm, int Ktot, u64_t acc[4][4], int r0, int cb, int tid)
{
    const int nb = Ktot >> 6;
    const int srow = tid >> 5, scol = (tid & 31) << 2;
    #pragma unroll
    for (int t = 0; t < 8; ++t)
        cpasync16(smaddr(Wsm + (srow + t * 8) * D + scol),
                  gW + (size_t)(srow + t * 8) * D + scol);
    cpcommit(); cpwait0(); __syncthreads();

    for (int b = 0; b < nb; ++b) {
        const float* cur = Wsm + (b & 1) * WBUF;
        if (b + 1 < nb) {
            const float* src = gW + (size_t)(b + 1) * 64 * D;
            float* dst = Wsm + ((b + 1) & 1) * WBUF;
            #pragma unroll
            for (int t = 0; t < 8; ++t)
                cpasync16(smaddr(dst + (srow + t * 8) * D + scol),
                          src + (size_t)(srow + t * 8) * D + scol);
            cpcommit();
        }
        const float* x0 = Xsm + (r0 + 0) * xld + (b << 6);
        const float* x1 = Xsm + (r0 + 1) * xld + (b << 6);
        const float* x2 = Xsm + (r0 + 2) * xld + (b << 6);
        const float* x3 = Xsm + (r0 + 3) * xld + (b << 6);
        #pragma unroll 2
        for (int k = 0; k < 64; k += 4) {
            float4 xr0 = *(const float4*)(x0 + k);
            float4 xr1 = *(const float4*)(x1 + k);
            float4 xr2 = *(const float4*)(x2 + k);
            float4 xr3 = *(const float4*)(x3 + k);
            #pragma unroll
            for (int kk = 0; kk < 4; ++kk) {
                ulonglong2 wA = *(const ulonglong2*)(cur + (k + kk) * D + cb);
                ulonglong2 wB = *(const ulonglong2*)(cur + (k + kk) * D + cb + 32);
                u64_t xa = pack2(f4get(xr0, kk)), xb = pack2(f4get(xr1, kk));
                u64_t xc = pack2(f4get(xr2, kk)), xd = pack2(f4get(xr3, kk));
                fma2(acc[0][0], xa, wA.x); fma2(acc[0][1], xa, wA.y);
                fma2(acc[0][2], xa, wB.x); fma2(acc[0][3], xa, wB.y);
                fma2(acc[1][0], xb, wA.x); fma2(acc[1][1], xb, wA.y);
                fma2(acc[1][2], xb, wB.x); fma2(acc[1][3], xb, wB.y);
                fma2(acc[2][0], xc, wA.x); fma2(acc[2][1], xc, wA.y);
                fma2(acc[2][2], xc, wB.x); fma2(acc[2][3], xc, wB.y);
                fma2(acc[3][0], xd, wA.x); fma2(acc[3][1], xd, wA.y);
                fma2(acc[3][2], xd, wB.x); fma2(acc[3][3], xd, wB.y);
            }
        }
        cpwait0(); __syncthreads();
    }
}

__device__ __forceinline__ void zero_acc(u64_t acc[4][4]) {
    #pragma unroll
    for (int i = 0; i < 4; ++i)
        #pragma unroll
        for (int p = 0; p < 4; ++p) acc[i][p] = 0ULL;
}
__device__ __forceinline__ void acc_to_f(u64_t acc[4][4], float a[4][8]) {
    #pragma unroll
    for (int i = 0; i < 4; ++i)
        #pragma unroll
        for (int p = 0; p < 4; ++p) unpack2(acc[i][p], a[i][2*p], a[i][2*p+1]);
}

__device__ __forceinline__ void layernorm_rows(float a[4][8],
    const float* __restrict__ g, const float* __restrict__ b,
    int cb, int col_warp, int r0, int lane, float2 (*smLN)[2])
{
    float4 g0 = *(const float4*)(g + cb), g1 = *(const float4*)(g + cb + 32);
    float4 b0 = *(const float4*)(b + cb), b1 = *(const float4*)(b + cb + 32);
    float gv[8] = {g0.x, g0.y, g0.z, g0.w, g1.x, g1.y, g1.z, g1.w};
    float bv[8] = {b0.x, b0.y, b0.z, b0.w, b1.x, b1.y, b1.z, b1.w};
    float s1[4], s2[4];
    #pragma unroll
    for (int i = 0; i < 4; ++i) {
        float s = 0.f, q = 0.f;
        #pragma unroll
        for (int j = 0; j < 8; ++j) { s += a[i][j]; q += a[i][j] * a[i][j]; }
        #pragma unroll
        for (int m = 1; m <= 4; m <<= 1) {
            s += __shfl_xor_sync(0xffffffffu, s, m);
            q += __shfl_xor_sync(0xffffffffu, q, m);
        }
        s1[i] = s; s2[i] = q;
    }
    if ((lane & 7) == 0) {
        #pragma unroll
        for (int i = 0; i < 4; ++i) smLN[r0 + i][col_warp] = make_float2(s1[i], s2[i]);
    }
    __syncthreads();
    #pragma unroll
    for (int i = 0; i < 4; ++i) {
        float2 pa = smLN[r0 + i][0], pb = smLN[r0 + i][1];
        float mean = (pa.x + pb.x) * 0.0078125f;
        float inv = rsqrtf((pa.y + pb.y) * 0.0078125f - mean * mean + 1e-5f);
        #pragma unroll
        for (int j = 0; j < 8; ++j) a[i][j] = (a[i][j] - mean) * inv * gv[j] + bv[j];
    }
}

__global__ void __launch_bounds__(NTHREADS) node_kernel(
    const float* __restrict__ node_feat,
    const float* __restrict__ w1c, const float* __restrict__ w2c,
    const float* __restrict__ w1g, const float* __restrict__ w2g,
    const float* __restrict__ lgc, const float* __restrict__ lbc,
    const float* __restrict__ lgg, const float* __restrict__ lbg,
    const float* __restrict__ node_res_w,
    float* __restrict__ out_node, int nN)
{
    extern __shared__ float sm[];
    float* Xsm = sm;
    float* Hsm = sm + TILE * XLD;
    float* Wsm = Hsm + TILE * HLD;
    __shared__ float2 smLN[TILE][2];

    int tid = threadIdx.x;
    int n0 = blockIdx.x * TILE;

    for (int idx = tid; idx < TILE * 96; idx += NTHREADS) {
        int r = idx / 96, p = idx % 96;
        int n = n0 + r;
        float4 v = {0.f, 0.f, 0.f, 0.f};
        if (n < nN) {
            if (p < 32) {
                v = *(const float4*)(node_feat + (size_t)n * D + p * 4);
            } else if (p < 64) {
                int o = (p - 32) * 4;
                float4 nu = *(const float4*)(g_num_tgt + (size_t)n * D + o);
                float4 de = *(const float4*)(g_den_tgt + (size_t)n * D + o);
                v.x = nu.x / (de.x + 1e-16f); v.y = nu.y / (de.y + 1e-16f);
                v.z = nu.z / (de.z + 1e-16f); v.w = nu.w / (de.w + 1e-16f);
            } else {
                int o = (p - 64) * 4;
                float4 nu = *(const float4*)(g_num_src + (size_t)n * D + o);
                float4 de = *(const float4*)(g_den_src + (size_t)n * D + o);
                v.x = nu.x / (de.x + 1e-16f); v.y = nu.y / (de.y + 1e-16f);
                v.z = nu.z / (de.z + 1e-16f); v.w = nu.w / (de.w + 1e-16f);
            }
        }
        *(float4*)(Xsm + r * XLD + p * 4) = v;
    }

    int wid = tid >> 5, lane = tid & 31;
    int row_warp = wid >> 1, col_warp = wid & 1;
    int ty = lane >> 3, tx = lane & 7;
    int r0 = row_warp * 16 + ty * 4;
    int cb = col_warp * 64 + tx * 4;

    u64_t acc[4][4];
    float a[4][8], attn[4][8];

    zero_acc(acc);
    gemm_tile(Xsm, XLD, w1c, Wsm, 384, acc, r0, cb, tid);
    acc_to_f(acc, a);
    #pragma unroll
    for (int i = 0; i < 4; ++i) {
        float4 h0 = {siluf(a[i][0]), siluf(a[i][1]), siluf(a[i][2]), siluf(a[i][3])};
        float4 h1 = {siluf(a[i][4]), siluf(a[i][5]), siluf(a[i][6]), siluf(a[i][7])};
        *(float4*)(Hsm + (r0 + i) * HLD + cb)      = h0;
        *(float4*)(Hsm + (r0 + i) * HLD + cb + 32) = h1;
    }
    zero_acc(acc);
    gemm_tile(Hsm, HLD, w2c, Wsm, 128, acc, r0, cb, tid);
    acc_to_f(acc, a);
    layernorm_rows(a, lgc, lbc, cb, col_warp, r0, lane, smLN);
    #pragma unroll
    for (int i = 0; i < 4; ++i)
        #pragma unroll
        for (int j = 0; j < 8; ++j) attn[i][j] = a[i][j];

    zero_acc(acc);
    gemm_tile(Xsm, XLD, w1g, Wsm, 384, acc, r0, cb, tid);
    acc_to_f(acc, a);
    #pragma unroll
    for (int i = 0; i < 4; ++i) {
        float4 h0 = {siluf(a[i][0]), siluf(a[i][1]), siluf(a[i][2]), siluf(a[i][3])};
        float4 h1 = {siluf(a[i][4]), siluf(a[i][5]), siluf(a[i][6]), siluf(a[i][7])};
        *(float4*)(Hsm + (r0 + i) * HLD + cb)      = h0;
        *(float4*)(Hsm + (r0 + i) * HLD + cb + 32) = h1;
    }
    zero_acc(acc);
    gemm_tile(Hsm, HLD, w2g, Wsm, 128, acc, r0, cb, tid);
    acc_to_f(acc, a);
    layernorm_rows(a, lgg, lbg, cb, col_warp, r0, lane, smLN);
    #pragma unroll
    for (int i = 0; i < 4; ++i)
        #pragma unroll
        for (int j = 0; j < 8; ++j)
            attn[i][j] = siluf(attn[i][j]) * sigmf(a[i][j]);

    float4 rw0 = *(const float4*)(node_res_w + cb);
    float4 rw1 = *(const float4*)(node_res_w + cb + 32);
    float rwv[8] = {rw0.x, rw0.y, rw0.z, rw0.w, rw1.x, rw1.y, rw1.z, rw1.w};
    #pragma unroll
    for (int i = 0; i < 4; ++i) {
        int n = n0 + r0 + i;
        if (n < nN) {
            const float* nfA = Xsm + (r0 + i) * XLD + cb;
            const float* nfB = nfA + 32;
            float4 o0 = {attn[i][0] + rwv[0]*nfA[0], attn[i][1] + rwv[1]*nfA[1],
                         attn[i][2] + rwv[2]*nfA[2], attn[i][3] + rwv[3]*nfA[3]};
            float4 o1 = {attn[i][4] + rwv[4]*nfB[0], attn[i][5] + rwv[5]*nfB[1],
                         attn[i][6] + rwv[6]*nfB[2], attn[i][7] + rwv[7]*nfB[3]};
            *(float4*)(out_node + (size_t)n * D + cb)      = o0;
            *(float4*)(out_node + (size_t)n * D + cb + 32) = o1;
        }
    }
}

// ---------------------------------------------------------------------------
extern "C" void kernel_launch(void* const* d_in, const int* in_sizes, int n_in,
                              void* d_out, int out_size)
{
    const float* node_feat = (const float*)d_in[0];
    const float* edge_feat = (const float*)d_in[1];
    const float* w_src     = (const float*)d_in[2];
    const float* w_tgt     = (const float*)d_in[3];
    const float* e_core_w1 = (const float*)d_in[4];
    const float* e_core_w2 = (const float*)d_in[5];
    const float* e_gate_w1 = (const float*)d_in[6];
    const float* e_gate_w2 = (const float*)d_in[7];
    const float* e_ln_cg   = (const float*)d_in[8];
    const float* e_ln_cb   = (const float*)d_in[9];
    const float* e_ln_gg   = (const float*)d_in[10];
    const float* e_ln_gb   = (const float*)d_in[11];
    const float* n_core_w1 = (const float*)d_in[12];
    const float* n_core_w2 = (const float*)d_in[13];
    const float* n_gate_w1 = (const float*)d_in[14];
    const float* n_gate_w2 = (const float*)d_in[15];
    const float* n_ln_cg   = (const float*)d_in[16];
    const float* n_ln_cb   = (const float*)d_in[17];
    const float* n_ln_gg   = (const float*)d_in[18];
    const float* n_ln_gb   = (const float*)d_in[19];
    const float* node_res_w= (const float*)d_in[20];
    const float* edge_res_w= (const float*)d_in[21];
    const int*   src_idx   = (const int*)d_in[22];
    const int*   tgt_idx   = (const int*)d_in[23];

    int nN = in_sizes[0] / D;
    int nE = in_sizes[1] / D;

    float* out_node = (float*)d_out;
    float* out_edge = out_node + (size_t)nN * D;

    cudaFuncSetAttribute(edge_mma_kernel, cudaFuncAttributeMaxDynamicSharedMemorySize, E_DYN);
    cudaFuncSetAttribute(node_kernel, cudaFuncAttributeMaxDynamicSharedMemorySize, SMEM_BYTES);

    prep_kernel<<<(nN * D + 255) / 256, 256>>>(w_src, w_tgt,
        e_core_w1, e_core_w2, e_gate_w1, e_gate_w2, nN);

    edge_mma_kernel<<<(nE + 63) / 64, 256, E_DYN>>>(
        node_feat, edge_feat,
        e_ln_cg, e_ln_cb, e_ln_gg, e_ln_gb,
        edge_res_w, src_idx, tgt_idx, out_edge, nE);

    node_kernel<<<(nN + TILE - 1) / TILE, NTHREADS, SMEM_BYTES>>>(
        node_feat,
        n_core_w1, n_core_w2, n_gate_w1, n_gate_w2,
        n_ln_cg, n_ln_cb, n_ln_gg, n_ln_gb,
        node_res_w, out_node, nN);
}

// round 13
// speedup vs baseline: 1.4711x; 1.0009x over previous
#include <cuda_runtime.h>
#include <cuda_bf16.h>

// ===========================================================================
// Graph attention layer. R6: edge path on mma.sync bf16 hi/lo (3-term);
// node path keeps R3 f32x2.
//   out = concat(attn_node [N,128], attn_edge [E,128])
// ===========================================================================

#define D        128
#define NMAX     10000

// ---- node path (R3) ----
#define TILE     64
#define XLD      388
#define HLD      132
#define NTHREADS 256
#define WBUF     (64 * D)
#define SMEM_BYTES ((TILE*XLD + TILE*HLD + 2*WBUF) * 4)

__device__ __align__(16) float g_num_src[NMAX * D];
__device__ __align__(16) float g_den_src[NMAX * D];
__device__ __align__(16) float g_num_tgt[NMAX * D];
__device__ __align__(16) float g_den_tgt[NMAX * D];
// fragment-ordered bf16 hi/lo weight images, 10 x [128 n][144 u32]:
// 0-2 e_core_w1 k-chunks, 3-5 e_gate_w1 k-chunks, 6 e_core_w2, 7 e_gate_w2,
// 8 w_src (as B[k][n]=w_src[n][k]), 9 w_tgt
__device__ __align__(16) unsigned g_wimg[10 * 18432];

typedef unsigned long long u64_t;

// ---------- common helpers ----------
__device__ __forceinline__ float siluf(float x)  { return x / (1.f + __expf(-x)); }
__device__ __forceinline__ float sigmf(float x)  { return 1.f / (1.f + __expf(-x)); }
__device__ __forceinline__ void red4(float* a, float x, float y, float z, float w) {
    asm volatile("red.global.add.v4.f32 [%0],{%1,%2,%3,%4};"
                 :: "l"(a), "f"(x), "f"(y), "f"(z), "f"(w) : "memory");
}
__device__ __forceinline__ unsigned smaddr(const void* p) {
    return (unsigned)__cvta_generic_to_shared(p);
}
__device__ __forceinline__ void cpasync16(unsigned dst, const void* src) {
    asm volatile("cp.async.cg.shared.global [%0], [%1], 16;" :: "r"(dst), "l"(src) : "memory");
}
__device__ __forceinline__ void cpcommit() { asm volatile("cp.async.commit_group;" ::: "memory"); }
__device__ __forceinline__ void cpwait0()  { asm volatile("cp.async.wait_group 0;" ::: "memory"); }

// pack (x0,x1) into bf16x2 hi and residual lo
__device__ __forceinline__ void pack_hl(float x0, float x1, unsigned& hi, unsigned& lo) {
    __nv_bfloat16 h0 = __float2bfloat16(x0), h1 = __float2bfloat16(x1);
    __nv_bfloat16 l0 = __float2bfloat16(x0 - __bfloat162float(h0));
    __nv_bfloat16 l1 = __float2bfloat16(x1 - __bfloat162float(h1));
    hi = (unsigned)__bfloat16_as_ushort(h0) | ((unsigned)__bfloat16_as_ushort(h1) << 16);
    lo = (unsigned)__bfloat16_as_ushort(l0) | ((unsigned)__bfloat16_as_ushort(l1) << 16);
}

// mma.sync m16n8k16 bf16: D += A*B
__device__ __forceinline__ void mma_bf16(float d[4], const unsigned a[4],
                                         unsigned b0, unsigned b1) {
    asm volatile("mma.sync.aligned.m16n8k16.row.col.f32.bf16.bf16.f32 "
        "{%0,%1,%2,%3},{%4,%5,%6,%7},{%8,%9},{%0,%1,%2,%3};"
        : "+f"(d[0]), "+f"(d[1]), "+f"(d[2]), "+f"(d[3])
        : "r"(a[0]), "r"(a[1]), "r"(a[2]), "r"(a[3]), "r"(b0), "r"(b1));
}

// ---- edge smem layout (u32 offsets). Row stride = 144 u32.
// Per row, per (ks,t): u32s [hi(kpair t), hi(kpair t+4), lo(t), lo(t+4)]
// at position ks*16 + t*4. kpair j -> ks=j>>3, tt=(j&7)&3, hf=(j&7)>>2:
// hi at ks*16+tt*4+hf, lo at +2.
#define STR   144
#define U_XE  0
#define U_XT  9216
#define U_XS  18432
#define U_H   27648
#define U_B   36864
#define E_UTOT 55296
#define E_DYN  (E_UTOT * 4)

__device__ __forceinline__ void st_pair(unsigned* rowbase, int j, float x0, float x1) {
    int ks = j >> 3, jj = j & 7, tt = jj & 3, hf = jj >> 2;
    unsigned hi, lo;
    pack_hl(x0, x1, hi, lo);
    rowbase[ks*16 + tt*4 + hf]     = hi;
    rowbase[ks*16 + tt*4 + hf + 2] = lo;
}

// stage a 64x128 fp32 block (optionally gathered rows) into frag-ordered smem
__device__ __forceinline__ void stage_X(unsigned* smu, int off, const float* base,
                                        const int* ridx, int e0, int nE, int tid) {
    int r = tid >> 2, part = tid & 3;
    long row = ridx ? (long)ridx[r] : (long)(e0 + r);
    bool ok = ridx ? true : ((e0 + r) < nE);
    const float* p = base + row * D + part * 32;
    unsigned* rb = smu + off + r * STR;
    #pragma unroll
    for (int q = 0; q < 8; ++q) {
        float4 v = ok ? __ldg((const float4*)(p + q * 4)) : make_float4(0.f,0.f,0.f,0.f);
        int j0 = part * 16 + q * 2;
        st_pair(rb, j0,     v.x, v.y);
        st_pair(rb, j0 + 1, v.z, v.w);
    }
}

// copy one weight image (73728 B) into B smem
__device__ __forceinline__ void stage_Bimg(unsigned* smu, int img, int tid) {
    unsigned dst = smaddr(smu + U_B);
    const char* src = (const char*)(g_wimg + (size_t)img * 18432);
    #pragma unroll
    for (int t = 0; t < 18; ++t) {
        int o = (tid + t * 256) * 16;
        cpasync16(dst + o, src + o);
    }
    cpcommit();
    cpwait0();
}

// acc[nt][0..3]: rows rw*16+g, rw*16+g+8 x cols cw*64+nt*8+2t, 2t+1
__device__ __forceinline__ void gemm_chunk(const unsigned* __restrict__ smu, int aoff,
                                           float acc[8][4], int rw, int cw, int lane) {
    int g = lane >> 2, t = lane & 3;
    const uint4* A0 = (const uint4*)(smu + aoff + (rw*16 + g) * STR);
    const uint4* A1 = (const uint4*)(smu + aoff + (rw*16 + g + 8) * STR);
    const uint4* B0 = (const uint4*)(smu + U_B + (cw*64 + g) * STR);
    #pragma unroll
    for (int ks = 0; ks < 8; ++ks) {
        uint4 ra0 = A0[ks*4 + t];
        uint4 ra1 = A1[ks*4 + t];
        unsigned Ah[4] = {ra0.x, ra1.x, ra0.y, ra1.y};
        unsigned Al[4] = {ra0.z, ra1.z, ra0.w, ra1.w};
        #pragma unroll
        for (int nt = 0; nt < 8; ++nt) {
            uint4 rb = B0[nt*8*(STR/4) + ks*4 + t];
            mma_bf16(acc[nt], Ah, rb.x, rb.y);
            mma_bf16(acc[nt], Ah, rb.z, rb.w);
            mma_bf16(acc[nt], Al, rb.x, rb.y);
        }
    }
}

__device__ __forceinline__ void zero8(float acc[8][4]) {
    #pragma unroll
    for (int i = 0; i < 8; ++i)
        #pragma unroll
        for (int p = 0; p < 4; ++p) acc[i][p] = 0.f;
}

// silu(acc) -> H smem (frag-ordered)
__device__ __forceinline__ void store_H(unsigned* smu, float acc[8][4],
                                        int rw, int cw, int lane) {
    int g = lane >> 2, t = lane & 3;
    unsigned* h0 = smu + U_H + (rw*16 + g) * STR;
    unsigned* h1 = h0 + 8 * STR;
    #pragma unroll
    for (int nt = 0; nt < 8; ++nt) {
        int j = cw*32 + nt*4 + t;
        st_pair(h0, j, siluf(acc[nt][0]), siluf(acc[nt][1]));
        st_pair(h1, j, siluf(acc[nt][2]), siluf(acc[nt][3]));
    }
}

// LayerNorm across 128 cols (2 col-warps combine via smLN); normalizes acc
__device__ __forceinline__ void ln_frags(float acc[8][4], int rw, int cw, int lane,
                                         const float* __restrict__ gma,
                                         const float* __restrict__ bta,
                                         float2 (*smLN)[2]) {
    int g = lane >> 2, t = lane & 3;
    float s0=0.f, q0=0.f, s1=0.f, q1=0.f;
    #pragma unroll
    for (int nt = 0; nt < 8; ++nt) {
        s0 += acc[nt][0] + acc[nt][1];
        q0 += acc[nt][0]*acc[nt][0] + acc[nt][1]*acc[nt][1];
        s1 += acc[nt][2] + acc[nt][3];
        q1 += acc[nt][2]*acc[nt][2] + acc[nt][3]*acc[nt][3];
    }
    #pragma unroll
    for (int m = 1; m <= 2; m <<= 1) {
        s0 += __shfl_xor_sync(0xffffffffu, s0, m);
        q0 += __shfl_xor_sync(0xffffffffu, q0, m);
        s1 += __shfl_xor_sync(0xffffffffu, s1, m);
        q1 += __shfl_xor_sync(0xffffffffu, q1, m);
    }
    int r0 = rw*16 + g;
    if (t == 0) {
        smLN[r0][cw]     = make_float2(s0, q0);
        smLN[r0 + 8][cw] = make_float2(s1, q1);
    }
    __syncthreads();
    float2 xa = smLN[r0][0], xb = smLN[r0][1];
    float mean0 = (xa.x + xb.x) * 0.0078125f;
    float inv0  = rsqrtf((xa.y + xb.y) * 0.0078125f - mean0*mean0 + 1e-5f);
    xa = smLN[r0 + 8][0]; xb = smLN[r0 + 8][1];
    float mean1 = (xa.x + xb.x) * 0.0078125f;
    float inv1  = rsqrtf((xa.y + xb.y) * 0.0078125f - mean1*mean1 + 1e-5f);
    #pragma unroll
    for (int nt = 0; nt < 8; ++nt) {
        int c = cw*64 + nt*8 + 2*t;
        float ga = __ldg(gma + c), gb = __ldg(gma + c + 1);
        float ba = __ldg(bta + c), bb = __ldg(bta + c + 1);
        acc[nt][0] = (acc[nt][0] - mean0) * inv0 * ga + ba;
        acc[nt][1] = (acc[nt][1] - mean0) * inv0 * gb + bb;
        acc[nt][2] = (acc[nt][2] - mean1) * inv1 * ga + ba;
        acc[nt][3] = (acc[nt][3] - mean1) * inv1 * gb + bb;
    }
}

// ===========================================================================
// prep: zero accumulators + build frag-ordered weight images
// ===========================================================================
__global__ void prep_kernel(const float* __restrict__ w_src,
                            const float* __restrict__ w_tgt,
                            const float* __restrict__ e1c,
                            const float* __restrict__ e2c,
                            const float* __restrict__ e1g,
                            const float* __restrict__ e2g, int nN)
{
    int i = blockIdx.x * blockDim.x + threadIdx.x;
    if (i < 10 * 8192) {
        int img = i >> 13;
        int rem = i & 8191;
        int n = rem >> 6, j = rem & 63;
        int k = 2 * j;
        float v0, v1;
        if (img < 3)       { v0 = e1c[(img*128 + k)*128 + n]; v1 = e1c[(img*128 + k + 1)*128 + n]; }
        else if (img < 6)  { int c = img - 3;
                             v0 = e1g[(c*128 + k)*128 + n];  v1 = e1g[(c*128 + k + 1)*128 + n]; }
        else if (img == 6) { v0 = e2c[k*128 + n];            v1 = e2c[(k + 1)*128 + n]; }
        else if (img == 7) { v0 = e2g[k*128 + n];            v1 = e2g[(k + 1)*128 + n]; }
        else if (img == 8) { v0 = w_src[n*128 + k];          v1 = w_src[n*128 + k + 1]; }
        else               { v0 = w_tgt[n*128 + k];          v1 = w_tgt[n*128 + k + 1]; }
        unsigned hi, lo;
        pack_hl(v0, v1, hi, lo);
        int ks = j >> 3, jj = j & 7, tt = jj & 3, hf = jj >> 2;
        int pos = img * 18432 + n * STR + ks*16 + tt*4 + hf;
        g_wimg[pos]     = hi;
        g_wimg[pos + 2] = lo;
    }
    if (i < nN * D) {
        g_num_src[i] = 0.f; g_den_src[i] = 0.f;
        g_num_tgt[i] = 0.f; g_den_tgt[i] = 0.f;
    }
}

// ===========================================================================
// edge kernel: 64 edges/CTA, 256 threads, mma.sync bf16 hi/lo
// ===========================================================================
__global__ void __launch_bounds__(256) edge_mma_kernel(
    const float* __restrict__ node_feat, const float* __restrict__ edge_feat,
    const float* __restrict__ lgc, const float* __restrict__ lbc,
    const float* __restrict__ lgg, const float* __restrict__ lbg,
    const float* __restrict__ edge_res_w,
    const int* __restrict__ src_idx, const int* __restrict__ tgt_idx,
    float* __restrict__ out_edge, int nE)
{
    extern __shared__ unsigned smu[];
    __shared__ int sidx[64], tidx[64];
    __shared__ float2 smLN[64][2];

    int tid = threadIdx.x;
    int wid = tid >> 5, lane = tid & 31;
    int rw = wid & 3, cw = wid >> 2;
    int e0 = blockIdx.x * 64;

    if (tid < 64) {
        int e = e0 + tid;
        sidx[tid] = (e < nE) ? src_idx[e] : 0;
        tidx[tid] = (e < nE) ? tgt_idx[e] : 0;
    }
    __syncthreads();

    stage_X(smu, U_XE, edge_feat, nullptr, e0, nE, tid);
    stage_X(smu, U_XT, node_feat, tidx, 0, 0, tid);
    stage_X(smu, U_XS, node_feat, sidx, 0, 0, tid);

    #define STAGEB(i) do { __syncthreads(); stage_Bimg(smu, i, tid); __syncthreads(); } while(0)

    float acc[8][4], cn[8][4];

    // ---- core branch ----
    zero8(acc);
    STAGEB(0); gemm_chunk(smu, U_XE, acc, rw, cw, lane);
    STAGEB(1); gemm_chunk(smu, U_XT, acc, rw, cw, lane);
    STAGEB(2); gemm_chunk(smu, U_XS, acc, rw, cw, lane);
    store_H(smu, acc, rw, cw, lane);
    zero8(acc);
    STAGEB(6); gemm_chunk(smu, U_H, acc, rw, cw, lane);
    ln_frags(acc, rw, cw, lane, lgc, lbc, smLN);
    #pragma unroll
    for (int nt = 0; nt < 8; ++nt)
        #pragma unroll
        for (int p = 0; p < 4; ++p) cn[nt][p] = acc[nt][p];

    // ---- gate branch ----
    zero8(acc);
    STAGEB(3); gemm_chunk(smu, U_XE, acc, rw, cw, lane);
    STAGEB(4); gemm_chunk(smu, U_XT, acc, rw, cw, lane);
    STAGEB(5); gemm_chunk(smu, U_XS, acc, rw, cw, lane);
    store_H(smu, acc, rw, cw, lane);
    zero8(acc);
    STAGEB(7); gemm_chunk(smu, U_H, acc, rw, cw, lane);
    ln_frags(acc, rw, cw, lane, lgg, lbg, smLN);
    #pragma unroll
    for (int nt = 0; nt < 8; ++nt)
        #pragma unroll
        for (int p = 0; p < 4; ++p) cn[nt][p] = siluf(cn[nt][p]) * sigmf(acc[nt][p]);

    // attn -> smem [64][stride 129] (reuse XT region)
    {
        float* at = (float*)(smu + U_XT);
        int g = lane >> 2, t = lane & 3;
        int r0 = rw*16 + g;
        #pragma unroll
        for (int nt = 0; nt < 8; ++nt) {
            int c = cw*64 + nt*8 + 2*t;
            at[r0*129 + c]       = cn[nt][0];
            at[r0*129 + c + 1]   = cn[nt][1];
            at[(r0+8)*129 + c]   = cn[nt][2];
            at[(r0+8)*129 + c+1] = cn[nt][3];
        }
    }

    // ---- z GEMMs ----
    zero8(acc);
    STAGEB(8); gemm_chunk(smu, U_XE, acc, rw, cw, lane);
    {
        float* z1 = (float*)(smu + U_XS);
        int g = lane >> 2, t = lane & 3;
        int r0 = rw*16 + g;
        #pragma unroll
        for (int nt = 0; nt < 8; ++nt) {
            int c = cw*64 + nt*8 + 2*t;
            z1[r0*129 + c]       = __expf(acc[nt][0]);
            z1[r0*129 + c + 1]   = __expf(acc[nt][1]);
            z1[(r0+8)*129 + c]   = __expf(acc[nt][2]);
            z1[(r0+8)*129 + c+1] = __expf(acc[nt][3]);
        }
    }
    zero8(acc);
    STAGEB(9); gemm_chunk(smu, U_XE, acc, rw, cw, lane);
    {
        float* z2 = (float*)(smu + U_H);
        int g = lane >> 2, t = lane & 3;
        int r0 = rw*16 + g;
        #pragma unroll
        for (int nt = 0; nt < 8; ++nt) {
            int c = cw*64 + nt*8 + 2*t;
            z2[r0*129 + c]       = __expf(acc[nt][0]);
            z2[r0*129 + c + 1]   = __expf(acc[nt][1]);
            z2[(r0+8)*129 + c]   = __expf(acc[nt][2]);
            z2[(r0+8)*129 + c+1] = __expf(acc[nt][3]);
        }
    }
    __syncthreads();

    // ---- pass C: out_edge = attn + edge_res_w * edge_feat (coalesced) ----
    const float* at = (const float*)(smu + U_XT);
    const float* z1 = (const float*)(smu + U_XS);
    const float* z2 = (const float*)(smu + U_H);
    for (int idx = tid; idx < 64 * 32; idx += 256) {
        int r2 = idx >> 5, q = (idx & 31) << 2;
        int e2 = e0 + r2;
        if (e2 < nE) {
            float4 ef = __ldg((const float4*)(edge_feat + (size_t)e2 * D + q));
            float4 rwv = __ldg((const float4*)(edge_res_w + q));
            const float* ap = at + r2*129 + q;
            float4 o = {ap[0] + rwv.x*ef.x, ap[1] + rwv.y*ef.y,
                        ap[2] + rwv.z*ef.z, ap[3] + rwv.w*ef.w};
            *(float4*)(out_edge + (size_t)e2 * D + q) = o;
        }
    }

    // ---- pass D: softmax num/den atomics ----
    for (int idx = tid; idx < 64 * 32; idx += 256) {
        int r2 = idx >> 5, q = (idx & 31) << 2;
        int e2 = e0 + r2;
        if (e2 < nE) {
            int ns = sidx[r2], ntg = tidx[r2];
            const float* ap = at + r2*129 + q;
            const float* p1 = z1 + r2*129 + q;
            const float* p2 = z2 + r2*129 + q;
            red4(g_den_src + (size_t)ns * D + q, p1[0], p1[1], p1[2], p1[3]);
            red4(g_num_src + (size_t)ns * D + q,
                 p1[0]*ap[0], p1[1]*ap[1], p1[2]*ap[2], p1[3]*ap[3]);
            red4(g_den_tgt + (size_t)ntg * D + q, p2[0], p2[1], p2[2], p2[3]);
            red4(g_num_tgt + (size_t)ntg * D + q,
                 p2[0]*ap[0], p2[1]*ap[1], p2[2]*ap[2], p2[3]*ap[3]);
        }
    }
    #undef STAGEB
}

// ===========================================================================
// node path (R3 f32x2) — unchanged
// ===========================================================================
__device__ __forceinline__ u64_t pack2(float x) {
    u64_t r; asm("mov.b64 %0,{%1,%1};" : "=l"(r) : "f"(x)); return r;
}
__device__ __forceinline__ void unpack2(u64_t v, float& lo, float& hi) {
    asm("mov.b64 {%0,%1},%2;" : "=f"(lo), "=f"(hi) : "l"(v));
}
__device__ __forceinline__ void fma2(u64_t& d, u64_t a, u64_t b) {
    asm("fma.rn.f32x2 %0,%1,%2,%0;" : "+l"(d) : "l"(a), "l"(b));
}
__device__ __forceinline__ float f4get(const float4& v, int i) {
    switch (i) { case 0: return v.x; case 1: return v.y; case 2: return v.z; default: return v.w; }
}

__device__ __forceinline__ void gemm_tile(
    const float* __restrict__ Xsm, int xld, const float* __restrict__ gW,
    float* __restrict__ Wsm, int Ktot, u64_t acc[4][4], int r0, int cb, int tid)
{
    const int nb = Ktot >> 6;
    const int srow = tid >> 5, scol = (tid & 31) << 2;
    #pragma unroll
    for (int t = 0; t < 8; ++t)
        cpasync16(smaddr(Wsm + (srow + t * 8) * D + scol),
                  gW + (size_t)(srow + t * 8) * D + scol);
    cpcommit(); cpwait0(); __syncthreads();

    for (int b = 0; b < nb; ++b) {
        const float* cur = Wsm + (b & 1) * WBUF;
        if (b + 1 < nb) {
            const float* src = gW + (size_t)(b + 1) * 64 * D;
            float* dst = Wsm + ((b + 1) & 1) * WBUF;
            #pragma unroll
            for (int t = 0; t < 8; ++t)
                cpasync16(smaddr(dst + (srow + t * 8) * D + scol),
                          src + (size_t)(srow + t * 8) * D + scol);
            cpcommit();
        }
        const float* x0 = Xsm + (r0 + 0) * xld + (b << 6);
        const float* x1 = Xsm + (r0 + 1) * xld + (b << 6);
        const float* x2 = Xsm + (r0 + 2) * xld + (b << 6);
        const float* x3 = Xsm + (r0 + 3) * xld + (b << 6);
        #pragma unroll 2
        for (int k = 0; k < 64; k += 4) {
            float4 xr0 = *(const float4*)(x0 + k);
            float4 xr1 = *(const float4*)(x1 + k);
            float4 xr2 = *(const float4*)(x2 + k);
            float4 xr3 = *(const float4*)(x3 + k);
            #pragma unroll
            for (int kk = 0; kk < 4; ++kk) {
                ulonglong2 wA = *(const ulonglong2*)(cur + (k + kk) * D + cb);
                ulonglong2 wB = *(const ulonglong2*)(cur + (k + kk) * D + cb + 32);
                u64_t xa = pack2(f4get(xr0, kk)), xb = pack2(f4get(xr1, kk));
                u64_t xc = pack2(f4get(xr2, kk)), xd = pack2(f4get(xr3, kk));
                fma2(acc[0][0], xa, wA.x); fma2(acc[0][1], xa, wA.y);
                fma2(acc[0][2], xa, wB.x); fma2(acc[0][3], xa, wB.y);
                fma2(acc[1][0], xb, wA.x); fma2(acc[1][1], xb, wA.y);
                fma2(acc[1][2], xb, wB.x); fma2(acc[1][3], xb, wB.y);
                fma2(acc[2][0], xc, wA.x); fma2(acc[2][1], xc, wA.y);
                fma2(acc[2][2], xc, wB.x); fma2(acc[2][3], xc, wB.y);
                fma2(acc[3][0], xd, wA.x); fma2(acc[3][1], xd, wA.y);
                fma2(acc[3][2], xd, wB.x); fma2(acc[3][3], xd, wB.y);
            }
        }
        cpwait0(); __syncthreads();
    }
}

__device__ __forceinline__ void zero_acc(u64_t acc[4][4]) {
    #pragma unroll
    for (int i = 0; i < 4; ++i)
        #pragma unroll
        for (int p = 0; p < 4; ++p) acc[i][p] = 0ULL;
}
__device__ __forceinline__ void acc_to_f(u64_t acc[4][4], float a[4][8]) {
    #pragma unroll
    for (int i = 0; i < 4; ++i)
        #pragma unroll
        for (int p = 0; p < 4; ++p) unpack2(acc[i][p], a[i][2*p], a[i][2*p+1]);
}

__device__ __forceinline__ void layernorm_rows(float a[4][8],
    const float* __restrict__ g, const float* __restrict__ b,
    int cb, int col_warp, int r0, int lane, float2 (*smLN)[2])
{
    float4 g0 = *(const float4*)(g + cb), g1 = *(const float4*)(g + cb + 32);
    float4 b0 = *(const float4*)(b + cb), b1 = *(const float4*)(b + cb + 32);
    float gv[8] = {g0.x, g0.y, g0.z, g0.w, g1.x, g1.y, g1.z, g1.w};
    float bv[8] = {b0.x, b0.y, b0.z, b0.w, b1.x, b1.y, b1.z, b1.w};
    float s1[4], s2[4];
    #pragma unroll
    for (int i = 0; i < 4; ++i) {
        float s = 0.f, q = 0.f;
        #pragma unroll
        for (int j = 0; j < 8; ++j) { s += a[i][j]; q += a[i][j] * a[i][j]; }
        #pragma unroll
        for (int m = 1; m <= 4; m <<= 1) {
            s += __shfl_xor_sync(0xffffffffu, s, m);
            q += __shfl_xor_sync(0xffffffffu, q, m);
        }
        s1[i] = s; s2[i] = q;
    }
    if ((lane & 7) == 0) {
        #pragma unroll
        for (int i = 0; i < 4; ++i) smLN[r0 + i][col_warp] = make_float2(s1[i], s2[i]);
    }
    __syncthreads();
    #pragma unroll
    for (int i = 0; i < 4; ++i) {
        float2 pa = smLN[r0 + i][0], pb = smLN[r0 + i][1];
        float mean = (pa.x + pb.x) * 0.0078125f;
        float inv = rsqrtf((pa.y + pb.y) * 0.0078125f - mean * mean + 1e-5f);
        #pragma unroll
        for (int j = 0; j < 8; ++j) a[i][j] = (a[i][j] - mean) * inv * gv[j] + bv[j];
    }
}

__global__ void __launch_bounds__(NTHREADS) node_kernel(
    const float* __restrict__ node_feat,
    const float* __restrict__ w1c, const float* __restrict__ w2c,
    const float* __restrict__ w1g, const float* __restrict__ w2g,
    const float* __restrict__ lgc, const float* __restrict__ lbc,
    const float* __restrict__ lgg, const float* __restrict__ lbg,
    const float* __restrict__ node_res_w,
    float* __restrict__ out_node, int nN)
{
    extern __shared__ float sm[];
    float* Xsm = sm;
    float* Hsm = sm + TILE * XLD;
    float* Wsm = Hsm + TILE * HLD;
    __shared__ float2 smLN[TILE][2];

    int tid = threadIdx.x;
    int n0 = blockIdx.x * TILE;

    for (int idx = tid; idx < TILE * 96; idx += NTHREADS) {
        int r = idx / 96, p = idx % 96;
        int n = n0 + r;
        float4 v = {0.f, 0.f, 0.f, 0.f};
        if (n < nN) {
            if (p < 32) {
                v = *(const float4*)(node_feat + (size_t)n * D + p * 4);
            } else if (p < 64) {
                int o = (p - 32) * 4;
                float4 nu = *(const float4*)(g_num_tgt + (size_t)n * D + o);
                float4 de = *(const float4*)(g_den_tgt + (size_t)n * D + o);
                v.x = nu.x / (de.x + 1e-16f); v.y = nu.y / (de.y + 1e-16f);
                v.z = nu.z / (de.z + 1e-16f); v.w = nu.w / (de.w + 1e-16f);
            } else {
                int o = (p - 64) * 4;
                float4 nu = *(const float4*)(g_num_src + (size_t)n * D + o);
                float4 de = *(const float4*)(g_den_src + (size_t)n * D + o);
                v.x = nu.x / (de.x + 1e-16f); v.y = nu.y / (de.y + 1e-16f);
                v.z = nu.z / (de.z + 1e-16f); v.w = nu.w / (de.w + 1e-16f);
            }
        }
        *(float4*)(Xsm + r * XLD + p * 4) = v;
    }

    int wid = tid >> 5, lane = tid & 31;
    int row_warp = wid >> 1, col_warp = wid & 1;
    int ty = lane >> 3, tx = lane & 7;
    int r0 = row_warp * 16 + ty * 4;
    int cb = col_warp * 64 + tx * 4;

    u64_t acc[4][4];
    float a[4][8], attn[4][8];

    zero_acc(acc);
    gemm_tile(Xsm, XLD, w1c, Wsm, 384, acc, r0, cb, tid);
    acc_to_f(acc, a);
    #pragma unroll
    for (int i = 0; i < 4; ++i) {
        float4 h0 = {siluf(a[i][0]), siluf(a[i][1]), siluf(a[i][2]), siluf(a[i][3])};
        float4 h1 = {siluf(a[i][4]), siluf(a[i][5]), siluf(a[i][6]), siluf(a[i][7])};
        *(float4*)(Hsm + (r0 + i) * HLD + cb)      = h0;
        *(float4*)(Hsm + (r0 + i) * HLD + cb + 32) = h1;
    }
    zero_acc(acc);
    gemm_tile(Hsm, HLD, w2c, Wsm, 128, acc, r0, cb, tid);
    acc_to_f(acc, a);
    layernorm_rows(a, lgc, lbc, cb, col_warp, r0, lane, smLN);
    #pragma unroll
    for (int i = 0; i < 4; ++i)
        #pragma unroll
        for (int j = 0; j < 8; ++j) attn[i][j] = a[i][j];

    zero_acc(acc);
    gemm_tile(Xsm, XLD, w1g, Wsm, 384, acc, r0, cb, tid);
    acc_to_f(acc, a);
    #pragma unroll
    for (int i = 0; i < 4; ++i) {
        float4 h0 = {siluf(a[i][0]), siluf(a[i][1]), siluf(a[i][2]), siluf(a[i][3])};
        float4 h1 = {siluf(a[i][4]), siluf(a[i][5]), siluf(a[i][6]), siluf(a[i][7])};
        *(float4*)(Hsm + (r0 + i) * HLD + cb)      = h0;
        *(float4*)(Hsm + (r0 + i) * HLD + cb + 32) = h1;
    }
    zero_acc(acc);
    gemm_tile(Hsm, HLD, w2g, Wsm, 128, acc, r0, cb, tid);
    acc_to_f(acc, a);
    layernorm_rows(a, lgg, lbg, cb, col_warp, r0, lane, smLN);
    #pragma unroll
    for (int i = 0; i < 4; ++i)
        #pragma unroll
        for (int j = 0; j < 8; ++j)
            attn[i][j] = siluf(attn[i][j]) * sigmf(a[i][j]);

    float4 rw0 = *(const float4*)(node_res_w + cb);
    float4 rw1 = *(const float4*)(node_res_w + cb + 32);
    float rwv[8] = {rw0.x, rw0.y, rw0.z, rw0.w, rw1.x, rw1.y, rw1.z, rw1.w};
    #pragma unroll
    for (int i = 0; i < 4; ++i) {
        int n = n0 + r0 + i;
        if (n < nN) {
            const float* nfA = Xsm + (r0 + i) * XLD + cb;
            const float* nfB = nfA + 32;
            float4 o0 = {attn[i][0] + rwv[0]*nfA[0], attn[i][1] + rwv[1]*nfA[1],
                         attn[i][2] + rwv[2]*nfA[2], attn[i][3] + rwv[3]*nfA[3]};
            float4 o1 = {attn[i][4] + rwv[4]*nfB[0], attn[i][5] + rwv[5]*nfB[1],
                         attn[i][6] + rwv[6]*nfB[2], attn[i][7] + rwv[7]*nfB[3]};
            *(float4*)(out_node + (size_t)n * D + cb)      = o0;
            *(float4*)(out_node + (size_t)n * D + cb + 32) = o1;
        }
    }
}

// ---------------------------------------------------------------------------
extern "C" void kernel_launch(void* const* d_in, const int* in_sizes, int n_in,
                              void* d_out, int out_size)
{
    const float* node_feat = (const float*)d_in[0];
    const float* edge_feat = (const float*)d_in[1];
    const float* w_src     = (const float*)d_in[2];
    const float* w_tgt     = (const float*)d_in[3];
    const float* e_core_w1 = (const float*)d_in[4];
    const float* e_core_w2 = (const float*)d_in[5];
    const float* e_gate_w1 = (const float*)d_in[6];
    const float* e_gate_w2 = (const float*)d_in[7];
    const float* e_ln_cg   = (const float*)d_in[8];
    const float* e_ln_cb   = (const float*)d_in[9];
    const float* e_ln_gg   = (const float*)d_in[10];
    const float* e_ln_gb   = (const float*)d_in[11];
    const float* n_core_w1 = (const float*)d_in[12];
    const float* n_core_w2 = (const float*)d_in[13];
    const float* n_gate_w1 = (const float*)d_in[14];
    const float* n_gate_w2 = (const float*)d_in[15];
    const float* n_ln_cg   = (const float*)d_in[16];
    const float* n_ln_cb   = (const float*)d_in[17];
    const float* n_ln_gg   = (const float*)d_in[18];
    const float* n_ln_gb   = (const float*)d_in[19];
    const float* node_res_w= (const float*)d_in[20];
    const float* edge_res_w= (const float*)d_in[21];
    const int*   src_idx   = (const int*)d_in[22];
    const int*   tgt_idx   = (const int*)d_in[23];

    int nN = in_sizes[0] / D;
    int nE = in_sizes[1] / D;

    float* out_node = (float*)d_out;
    float* out_edge = out_node + (size_t)nN * D;

    cudaFuncSetAttribute(edge_mma_kernel, cudaFuncAttributeMaxDynamicSharedMemorySize, E_DYN);
    cudaFuncSetAttribute(node_kernel, cudaFuncAttributeMaxDynamicSharedMemorySize, SMEM_BYTES);

    prep_kernel<<<(nN * D + 255) / 256, 256>>>(w_src, w_tgt,
        e_core_w1, e_core_w2, e_gate_w1, e_gate_w2, nN);

    edge_mma_kernel<<<(nE + 63) / 64, 256, E_DYN>>>(
        node_feat, edge_feat,
        e_ln_cg, e_ln_cb, e_ln_gg, e_ln_gb,
        edge_res_w, src_idx, tgt_idx, out_edge, nE);

    node_kernel<<<(nN + TILE - 1) / TILE, NTHREADS, SMEM_BYTES>>>(
        node_feat,
        n_core_w1, n_core_w2, n_gate_w1, n_gate_w2,
        n_ln_cg, n_ln_cb, n_ln_gg, n_ln_gb,
        node_res_w, out_node, nN);
}